// round 1
// baseline (speedup 1.0000x reference)
#include <cuda_runtime.h>
#include <cstdint>

#define NNODES 50000
#define HDIM   256

// ---------------- scratch (no allocations allowed) ----------------
__device__ float g_bufA[NNODES * HDIM];
__device__ float g_bufB[NNODES * HDIM];
__device__ float g_bufC[NNODES * HDIM];
__device__ int   g_deg[NNODES];
__device__ float g_dinv[NNODES];

// ---------------- degree / dinv ----------------
__global__ void deg_zero_kernel(int* __restrict__ deg, int n) {
    int i = blockIdx.x * blockDim.x + threadIdx.x;
    if (i < n) deg[i] = 0;
}

__global__ void deg_count_kernel(int* __restrict__ deg, const int* __restrict__ dst, int E) {
    int e = blockIdx.x * blockDim.x + threadIdx.x;
    if (e < E) atomicAdd(&deg[dst[e]], 1);
}

__global__ void dinv_kernel(float* __restrict__ dinv, const int* __restrict__ deg, int n) {
    int i = blockIdx.x * blockDim.x + threadIdx.x;
    if (i < n) dinv[i] = rsqrtf((float)(deg[i] + 1));  // +1 self-loop
}

// ---------------- SGEMM: C[M,256] = A[M,K] @ W[K,256] (+bias) ----------------
// 64x64 block tile, BK=16, 256 threads, 4x4 microtile.
// RELU_A applies relu to A elements on load (fuses previous layer's activation).
template <int K, bool BIAS, bool RELU_A>
__global__ void __launch_bounds__(256) gemm64_kernel(
    const float* __restrict__ A, const float* __restrict__ W,
    const float* __restrict__ bias, float* __restrict__ C, int M)
{
    __shared__ float As[16][64];   // [k][m]
    __shared__ float Bs[16][64];   // [k][n]

    const int tid = threadIdx.x;
    const int tx  = tid & 15;      // 0..15 -> col group
    const int ty  = tid >> 4;      // 0..15 -> row group
    const int row0 = blockIdx.x * 64;
    const int col0 = blockIdx.y * 64;

    // A-load mapping: 64 rows x 16 k, one float4 per thread
    const int la_r = tid >> 2;          // 0..63
    const int la_c = (tid & 3) * 4;     // 0,4,8,12
    // B-load mapping: 16 k x 64 cols, one float4 per thread
    const int lb_r = tid >> 4;          // 0..15
    const int lb_c = (tid & 15) * 4;    // 0..60

    float acc[4][4];
#pragma unroll
    for (int i = 0; i < 4; i++)
#pragma unroll
        for (int j = 0; j < 4; j++) acc[i][j] = 0.f;

    const int arow = row0 + la_r;
    const bool a_ok = (arow < M);

    for (int k0 = 0; k0 < K; k0 += 16) {
        float4 av = make_float4(0.f, 0.f, 0.f, 0.f);
        if (a_ok) av = *(const float4*)(A + (size_t)arow * K + k0 + la_c);
        if (RELU_A) {
            av.x = fmaxf(av.x, 0.f); av.y = fmaxf(av.y, 0.f);
            av.z = fmaxf(av.z, 0.f); av.w = fmaxf(av.w, 0.f);
        }
        As[la_c + 0][la_r] = av.x;
        As[la_c + 1][la_r] = av.y;
        As[la_c + 2][la_r] = av.z;
        As[la_c + 3][la_r] = av.w;

        float4 bv = *(const float4*)(W + (size_t)(k0 + lb_r) * HDIM + col0 + lb_c);
        *(float4*)&Bs[lb_r][lb_c] = bv;

        __syncthreads();

#pragma unroll
        for (int k = 0; k < 16; k++) {
            float4 a4 = *(const float4*)&As[k][ty * 4];
            float4 b4 = *(const float4*)&Bs[k][tx * 4];
            float a[4] = {a4.x, a4.y, a4.z, a4.w};
            float b[4] = {b4.x, b4.y, b4.z, b4.w};
#pragma unroll
            for (int i = 0; i < 4; i++)
#pragma unroll
                for (int j = 0; j < 4; j++)
                    acc[i][j] = fmaf(a[i], b[j], acc[i][j]);
        }
        __syncthreads();
    }

#pragma unroll
    for (int i = 0; i < 4; i++) {
        int r = row0 + ty * 4 + i;
        if (r < M) {
            float* crow = C + (size_t)r * HDIM + col0 + tx * 4;
            float4 v = {acc[i][0], acc[i][1], acc[i][2], acc[i][3]};
            if (BIAS) {
                const float4 bb = *(const float4*)(bias + col0 + tx * 4);
                v.x += bb.x; v.y += bb.y; v.z += bb.z; v.w += bb.w;
            }
            *(float4*)crow = v;
        }
    }
}

// ---------------- self-loop + bias init (non-atomic) ----------------
// out[i,j] = hw[i,j] * dinv[i]^2 + bias[j]
__global__ void init_out_kernel(float* __restrict__ out, const float* __restrict__ hw,
                                const float* __restrict__ dinv, const float* __restrict__ bias,
                                int M)
{
    int idx = blockIdx.x * blockDim.x + threadIdx.x;   // over M*64 float4s
    int total = M * (HDIM / 4);
    if (idx >= total) return;
    int row = idx >> 6;
    int c4  = (idx & 63) * 4;
    float di = dinv[row];
    float s = di * di;
    float4 h = *(const float4*)(hw + (size_t)row * HDIM + c4);
    float4 b = *(const float4*)(bias + c4);
    float4 o;
    o.x = fmaf(h.x, s, b.x);
    o.y = fmaf(h.y, s, b.y);
    o.z = fmaf(h.z, s, b.z);
    o.w = fmaf(h.w, s, b.w);
    *(float4*)(out + (size_t)row * HDIM + c4) = o;
}

// ---------------- edge scatter: out[d] += hw[s] * dinv[s]*dinv[d] ----------------
// one warp per edge; 2x (LDG.128 + RED.128) per lane
__global__ void __launch_bounds__(256) scatter_kernel(
    float* __restrict__ out, const float* __restrict__ hw,
    const int* __restrict__ src, const int* __restrict__ dst,
    const float* __restrict__ dinv, int E)
{
    int e = blockIdx.x * (blockDim.x >> 5) + (threadIdx.x >> 5);
    if (e >= E) return;
    int lane = threadIdx.x & 31;
    int s = __ldg(&src[e]);
    int d = __ldg(&dst[e]);
    float norm = dinv[s] * dinv[d];
    const float4* a = (const float4*)(hw + (size_t)s * HDIM);
    float4*       o = (float4*)(out + (size_t)d * HDIM);
#pragma unroll
    for (int i = 0; i < 2; i++) {
        float4 v = a[lane + 32 * i];
        v.x *= norm; v.y *= norm; v.z *= norm; v.w *= norm;
        asm volatile("red.global.add.v4.f32 [%0], {%1,%2,%3,%4};"
                     :: "l"(o + lane + 32 * i), "f"(v.x), "f"(v.y), "f"(v.z), "f"(v.w)
                     : "memory");
    }
}

// ---------------- decoder: out[i] = relu(h[i,:]) . dec_W + dec_b ----------------
__global__ void __launch_bounds__(256) decoder_kernel(
    const float* __restrict__ h, const float* __restrict__ dw,
    const float* __restrict__ db, float* __restrict__ out, int M)
{
    int row  = blockIdx.x * (blockDim.x >> 5) + (threadIdx.x >> 5);
    int lane = threadIdx.x & 31;
    if (row >= M) return;
    const float* hr = h + (size_t)row * HDIM;
    float s = 0.f;
#pragma unroll
    for (int i = 0; i < 8; i++) {
        float v = fmaxf(hr[lane + i * 32], 0.f);
        s = fmaf(v, __ldg(&dw[lane + i * 32]), s);
    }
#pragma unroll
    for (int o = 16; o > 0; o >>= 1) s += __shfl_xor_sync(0xffffffffu, s, o);
    if (lane == 0) out[row] = s + db[0];
}

// ---------------- launch ----------------
extern "C" void kernel_launch(void* const* d_in, const int* in_sizes, int n_in,
                              void* d_out, int out_size)
{
    const float* x     = (const float*)d_in[0];
    const int*   ei    = (const int*)d_in[1];
    const float* enc_W = (const float*)d_in[2];
    const float* enc_b = (const float*)d_in[3];
    const float* W1    = (const float*)d_in[4];
    const float* b1    = (const float*)d_in[5];
    const float* W2    = (const float*)d_in[6];
    const float* b2    = (const float*)d_in[7];
    const float* W3    = (const float*)d_in[8];
    const float* b3    = (const float*)d_in[9];
    const float* decW  = (const float*)d_in[10];
    const float* decb  = (const float*)d_in[11];
    float* out = (float*)d_out;

    const int M = in_sizes[0] / 128;   // 50000
    const int E = in_sizes[1] / 2;     // 800000
    const int* src = ei;
    const int* dst = ei + E;

    float *bufA, *bufB, *bufC, *dinv;
    int* deg;
    cudaGetSymbolAddress((void**)&bufA, g_bufA);
    cudaGetSymbolAddress((void**)&bufB, g_bufB);
    cudaGetSymbolAddress((void**)&bufC, g_bufC);
    cudaGetSymbolAddress((void**)&deg,  g_deg);
    cudaGetSymbolAddress((void**)&dinv, g_dinv);

    // degrees (shared by all convs)
    deg_zero_kernel<<<(M + 255) / 256, 256>>>(deg, M);
    deg_count_kernel<<<(E + 255) / 256, 256>>>(deg, dst, E);
    dinv_kernel<<<(M + 255) / 256, 256>>>(dinv, deg, M);

    const dim3 ggrid((M + 63) / 64, HDIM / 64);
    const int init_blocks = (M * (HDIM / 4) + 255) / 256;
    const int scat_blocks = (E + 7) / 8;

    // encoder: bufA = x @ enc_W + enc_b
    gemm64_kernel<128, true, false><<<ggrid, 256>>>(x, enc_W, enc_b, bufA, M);

    // conv1: bufB = bufA @ W1 ; bufC = selfloop+b1 ; scatter edges
    gemm64_kernel<256, false, false><<<ggrid, 256>>>(bufA, W1, nullptr, bufB, M);
    init_out_kernel<<<init_blocks, 256>>>(bufC, bufB, dinv, b1, M);
    scatter_kernel<<<scat_blocks, 256>>>(bufC, bufB, src, dst, dinv, E);

    // conv2 (relu on input fused into GEMM A-load)
    gemm64_kernel<256, false, true><<<ggrid, 256>>>(bufC, W2, nullptr, bufB, M);
    init_out_kernel<<<init_blocks, 256>>>(bufA, bufB, dinv, b2, M);
    scatter_kernel<<<scat_blocks, 256>>>(bufA, bufB, src, dst, dinv, E);

    // conv3
    gemm64_kernel<256, false, true><<<ggrid, 256>>>(bufA, W3, nullptr, bufB, M);
    init_out_kernel<<<init_blocks, 256>>>(bufC, bufB, dinv, b3, M);
    scatter_kernel<<<scat_blocks, 256>>>(bufC, bufB, src, dst, dinv, E);

    // decoder (relu fused)
    decoder_kernel<<<(M + 7) / 8, 256>>>(bufC, decW, decb, out, M);
}

// round 3
// speedup vs baseline: 1.2841x; 1.2841x over previous
#include <cuda_runtime.h>
#include <cstdint>

#define NNODES 50000
#define EDGES  800000
#define HDIM   256

// ---------------- scratch (no allocations allowed) ----------------
__device__ float g_bufA[NNODES * HDIM];
__device__ float g_bufB[NNODES * HDIM];
__device__ float g_bufC[NNODES * HDIM];
__device__ int   g_deg[NNODES];
__device__ float g_dinv[NNODES];
__device__ int   g_offs[NNODES + 1];
__device__ int   g_cur[NNODES];
__device__ int   g_csr_src[EDGES];
__device__ float g_csr_w[EDGES];

// ---------------- degree / dinv ----------------
__global__ void deg_zero_kernel(int* __restrict__ deg, int n) {
    int i = blockIdx.x * blockDim.x + threadIdx.x;
    if (i < n) deg[i] = 0;
}

__global__ void deg_count_kernel(int* __restrict__ deg, const int* __restrict__ dst, int E) {
    int e = blockIdx.x * blockDim.x + threadIdx.x;
    if (e < E) atomicAdd(&deg[dst[e]], 1);
}

__global__ void dinv_kernel(float* __restrict__ dinv, const int* __restrict__ deg, int n) {
    int i = blockIdx.x * blockDim.x + threadIdx.x;
    if (i < n) dinv[i] = rsqrtf((float)(deg[i] + 1));  // +1 self-loop
}

// ---------------- exclusive scan (single block, 1024 threads) ----------------
__global__ void scan_kernel(int* __restrict__ offs, int* __restrict__ cur,
                            const int* __restrict__ deg, int n)
{
    __shared__ int sh[1024];
    const int t = threadIdx.x;
    int running = 0;
    for (int base = 0; base < n; base += 1024) {
        int v = (base + t < n) ? deg[base + t] : 0;
        sh[t] = v;
        __syncthreads();
#pragma unroll
        for (int off = 1; off < 1024; off <<= 1) {
            int x = (t >= off) ? sh[t - off] : 0;
            __syncthreads();
            sh[t] += x;
            __syncthreads();
        }
        if (base + t < n) {
            int excl = running + sh[t] - v;
            offs[base + t] = excl;
            cur[base + t]  = excl;
        }
        running += sh[1023];
        __syncthreads();
    }
    if (t == 0) offs[n] = running;
}

// ---------------- CSR fill ----------------
__global__ void csr_fill_kernel(int* __restrict__ cur, int* __restrict__ csr_src,
                                const int* __restrict__ src, const int* __restrict__ dst, int E)
{
    int e = blockIdx.x * blockDim.x + threadIdx.x;
    if (e >= E) return;
    int p = atomicAdd(&cur[dst[e]], 1);
    csr_src[p] = src[e];
}

__global__ void csr_w_kernel(float* __restrict__ csr_w, const int* __restrict__ csr_src,
                             const float* __restrict__ dinv, int E)
{
    int e = blockIdx.x * blockDim.x + threadIdx.x;
    if (e < E) csr_w[e] = dinv[csr_src[e]];
}

// ---------------- SGEMM: C[M,256] = A[M,K] @ W[K,256] (+bias) ----------------
// 128x128 tile, BK=8, 256 threads, 8x8 microtile, double-buffered smem.
template <int K, bool BIAS, bool RELU_A>
__global__ void __launch_bounds__(256, 2) gemm128_kernel(
    const float* __restrict__ A, const float* __restrict__ W,
    const float* __restrict__ bias, float* __restrict__ C, int M)
{
    __shared__ float As[2][8][132];   // [buf][k][m], padded to avoid STS conflicts
    __shared__ float Bs[2][8][128];   // [buf][k][n]

    const int tid = threadIdx.x;
    const int row0 = blockIdx.x * 128;
    const int col0 = blockIdx.y * 128;

    // A load: 128 rows x 8 k per tile -> 1 float4/thread
    const int ar = tid >> 1;            // 0..127
    const int ak = (tid & 1) * 4;       // 0 or 4
    // B load: 8 k x 128 cols -> 1 float4/thread
    const int bk = tid >> 5;            // 0..7
    const int bc = (tid & 31) * 4;      // 0..124

    const int tx = tid & 15;            // col 8-group
    const int ty = tid >> 4;            // row 8-group

    const int arow = row0 + ar;
    const bool a_ok = (arow < M);
    const float* Aptr = A + (size_t)arow * K + ak;
    const float* Wptr = W + (size_t)bk * HDIM + col0 + bc;

    float acc[8][8];
#pragma unroll
    for (int i = 0; i < 8; i++)
#pragma unroll
        for (int j = 0; j < 8; j++) acc[i][j] = 0.f;

    constexpr int NT = K / 8;

    // prefetch tile 0
    float4 av = make_float4(0.f, 0.f, 0.f, 0.f);
    if (a_ok) av = *(const float4*)(Aptr);
    float4 bv = *(const float4*)(Wptr);

    // store tile 0
    {
        float4 t = av;
        if (RELU_A) {
            t.x = fmaxf(t.x, 0.f); t.y = fmaxf(t.y, 0.f);
            t.z = fmaxf(t.z, 0.f); t.w = fmaxf(t.w, 0.f);
        }
        As[0][ak + 0][ar] = t.x;
        As[0][ak + 1][ar] = t.y;
        As[0][ak + 2][ar] = t.z;
        As[0][ak + 3][ar] = t.w;
        *(float4*)&Bs[0][bk][bc] = bv;
    }
    __syncthreads();

    for (int it = 0; it < NT; it++) {
        const int buf = it & 1;
        if (it + 1 < NT) {
            if (a_ok) av = *(const float4*)(Aptr + (it + 1) * 8);
            bv = *(const float4*)(Wptr + (size_t)(it + 1) * 8 * HDIM);
        }
#pragma unroll
        for (int kk = 0; kk < 8; kk++) {
            float4 x0 = *(const float4*)&As[buf][kk][ty * 8];
            float4 x1 = *(const float4*)&As[buf][kk][ty * 8 + 4];
            float4 y0 = *(const float4*)&Bs[buf][kk][tx * 8];
            float4 y1 = *(const float4*)&Bs[buf][kk][tx * 8 + 4];
            float a[8] = {x0.x, x0.y, x0.z, x0.w, x1.x, x1.y, x1.z, x1.w};
            float b[8] = {y0.x, y0.y, y0.z, y0.w, y1.x, y1.y, y1.z, y1.w};
#pragma unroll
            for (int i = 0; i < 8; i++)
#pragma unroll
                for (int j = 0; j < 8; j++)
                    acc[i][j] = fmaf(a[i], b[j], acc[i][j]);
        }
        if (it + 1 < NT) {
            const int nb = buf ^ 1;
            float4 t = av;
            if (RELU_A) {
                t.x = fmaxf(t.x, 0.f); t.y = fmaxf(t.y, 0.f);
                t.z = fmaxf(t.z, 0.f); t.w = fmaxf(t.w, 0.f);
            }
            As[nb][ak + 0][ar] = t.x;
            As[nb][ak + 1][ar] = t.y;
            As[nb][ak + 2][ar] = t.z;
            As[nb][ak + 3][ar] = t.w;
            *(float4*)&Bs[nb][bk][bc] = bv;
            __syncthreads();
        }
    }

    // epilogue
#pragma unroll
    for (int i = 0; i < 8; i++) {
        int r = row0 + ty * 8 + i;
        if (r < M) {
            float* crow = C + (size_t)r * HDIM + col0 + tx * 8;
            float4 v0 = {acc[i][0], acc[i][1], acc[i][2], acc[i][3]};
            float4 v1 = {acc[i][4], acc[i][5], acc[i][6], acc[i][7]};
            if (BIAS) {
                const float4 bb0 = *(const float4*)(bias + col0 + tx * 8);
                const float4 bb1 = *(const float4*)(bias + col0 + tx * 8 + 4);
                v0.x += bb0.x; v0.y += bb0.y; v0.z += bb0.z; v0.w += bb0.w;
                v1.x += bb1.x; v1.y += bb1.y; v1.z += bb1.z; v1.w += bb1.w;
            }
            *(float4*)crow = v0;
            *(float4*)(crow + 4) = v1;
        }
    }
}

// ---------------- gather conv: out[d] = (Σ_in hw[s]·dinv[s])·dinv[d] + hw[d]·dinv[d]² + bias ----------------
// 2 warps per node (128 cols each); register accumulation, single write.
__global__ void __launch_bounds__(256) gather_kernel(
    float* __restrict__ out, const float* __restrict__ hw,
    const int* __restrict__ offs, const int* __restrict__ csr_src,
    const float* __restrict__ csr_w, const float* __restrict__ dinv,
    const float* __restrict__ bias, int M)
{
    const int gw   = blockIdx.x * (blockDim.x >> 5) + (threadIdx.x >> 5);
    const int node = gw >> 1;
    if (node >= M) return;
    const int lane = threadIdx.x & 31;
    const int col  = (gw & 1) * 128 + lane * 4;

    const int beg = offs[node];
    const int end = offs[node + 1];

    float4 acc = make_float4(0.f, 0.f, 0.f, 0.f);
    int j = beg;
    for (; j + 1 < end; j += 2) {
        int s0 = csr_src[j], s1 = csr_src[j + 1];
        float w0 = csr_w[j], w1 = csr_w[j + 1];
        float4 v0 = *(const float4*)(hw + (size_t)s0 * HDIM + col);
        float4 v1 = *(const float4*)(hw + (size_t)s1 * HDIM + col);
        acc.x = fmaf(w0, v0.x, acc.x); acc.y = fmaf(w0, v0.y, acc.y);
        acc.z = fmaf(w0, v0.z, acc.z); acc.w = fmaf(w0, v0.w, acc.w);
        acc.x = fmaf(w1, v1.x, acc.x); acc.y = fmaf(w1, v1.y, acc.y);
        acc.z = fmaf(w1, v1.z, acc.z); acc.w = fmaf(w1, v1.w, acc.w);
    }
    if (j < end) {
        int s0 = csr_src[j];
        float w0 = csr_w[j];
        float4 v0 = *(const float4*)(hw + (size_t)s0 * HDIM + col);
        acc.x = fmaf(w0, v0.x, acc.x); acc.y = fmaf(w0, v0.y, acc.y);
        acc.z = fmaf(w0, v0.z, acc.z); acc.w = fmaf(w0, v0.w, acc.w);
    }

    const float dd = dinv[node];
    const float ds = dd * dd;
    float4 self = *(const float4*)(hw + (size_t)node * HDIM + col);
    float4 bb   = *(const float4*)(bias + col);
    float4 o;
    o.x = fmaf(acc.x, dd, fmaf(self.x, ds, bb.x));
    o.y = fmaf(acc.y, dd, fmaf(self.y, ds, bb.y));
    o.z = fmaf(acc.z, dd, fmaf(self.z, ds, bb.z));
    o.w = fmaf(acc.w, dd, fmaf(self.w, ds, bb.w));
    *(float4*)(out + (size_t)node * HDIM + col) = o;
}

// ---------------- decoder: out[i] = relu(h[i,:]) . dec_W + dec_b ----------------
__global__ void __launch_bounds__(256) decoder_kernel(
    const float* __restrict__ h, const float* __restrict__ dw,
    const float* __restrict__ db, float* __restrict__ out, int M)
{
    int row  = blockIdx.x * (blockDim.x >> 5) + (threadIdx.x >> 5);
    int lane = threadIdx.x & 31;
    if (row >= M) return;
    const float* hr = h + (size_t)row * HDIM;
    float s = 0.f;
#pragma unroll
    for (int i = 0; i < 8; i++) {
        float v = fmaxf(hr[lane + i * 32], 0.f);
        s = fmaf(v, __ldg(&dw[lane + i * 32]), s);
    }
#pragma unroll
    for (int o = 16; o > 0; o >>= 1) s += __shfl_xor_sync(0xffffffffu, s, o);
    if (lane == 0) out[row] = s + db[0];
}

// ---------------- launch ----------------
extern "C" void kernel_launch(void* const* d_in, const int* in_sizes, int n_in,
                              void* d_out, int out_size)
{
    const float* x     = (const float*)d_in[0];
    const int*   ei    = (const int*)d_in[1];
    const float* enc_W = (const float*)d_in[2];
    const float* enc_b = (const float*)d_in[3];
    const float* W1    = (const float*)d_in[4];
    const float* b1    = (const float*)d_in[5];
    const float* W2    = (const float*)d_in[6];
    const float* b2    = (const float*)d_in[7];
    const float* W3    = (const float*)d_in[8];
    const float* b3    = (const float*)d_in[9];
    const float* decW  = (const float*)d_in[10];
    const float* decb  = (const float*)d_in[11];
    float* out = (float*)d_out;

    const int M = in_sizes[0] / 128;   // 50000
    const int E = in_sizes[1] / 2;     // 800000
    const int* src = ei;
    const int* dst = ei + E;

    float *bufA, *bufB, *bufC, *dinv, *csr_w;
    int *deg, *offs, *cur, *csr_src;
    cudaGetSymbolAddress((void**)&bufA,    g_bufA);
    cudaGetSymbolAddress((void**)&bufB,    g_bufB);
    cudaGetSymbolAddress((void**)&bufC,    g_bufC);
    cudaGetSymbolAddress((void**)&deg,     g_deg);
    cudaGetSymbolAddress((void**)&dinv,    g_dinv);
    cudaGetSymbolAddress((void**)&offs,    g_offs);
    cudaGetSymbolAddress((void**)&cur,     g_cur);
    cudaGetSymbolAddress((void**)&csr_src, g_csr_src);
    cudaGetSymbolAddress((void**)&csr_w,   g_csr_w);

    // ---- graph preprocessing (once per call, reused by 3 convs) ----
    deg_zero_kernel<<<(M + 255) / 256, 256>>>(deg, M);
    deg_count_kernel<<<(E + 255) / 256, 256>>>(deg, dst, E);
    dinv_kernel<<<(M + 255) / 256, 256>>>(dinv, deg, M);
    scan_kernel<<<1, 1024>>>(offs, cur, deg, M);
    csr_fill_kernel<<<(E + 255) / 256, 256>>>(cur, csr_src, src, dst, E);
    csr_w_kernel<<<(E + 255) / 256, 256>>>(csr_w, csr_src, dinv, E);

    const dim3 ggrid((M + 127) / 128, HDIM / 128);
    const int gat_blocks = (2 * M + 7) / 8;

    // encoder: bufA = x @ enc_W + enc_b
    gemm128_kernel<128, true, false><<<ggrid, 256>>>(x, enc_W, enc_b, bufA, M);

    // conv1
    gemm128_kernel<256, false, false><<<ggrid, 256>>>(bufA, W1, nullptr, bufB, M);
    gather_kernel<<<gat_blocks, 256>>>(bufC, bufB, offs, csr_src, csr_w, dinv, b1, M);

    // conv2 (relu fused into GEMM A-load)
    gemm128_kernel<256, false, true><<<ggrid, 256>>>(bufC, W2, nullptr, bufB, M);
    gather_kernel<<<gat_blocks, 256>>>(bufA, bufB, offs, csr_src, csr_w, dinv, b2, M);

    // conv3
    gemm128_kernel<256, false, true><<<ggrid, 256>>>(bufA, W3, nullptr, bufB, M);
    gather_kernel<<<gat_blocks, 256>>>(bufC, bufB, offs, csr_src, csr_w, dinv, b3, M);

    // decoder (relu fused)
    decoder_kernel<<<(M + 7) / 8, 256>>>(bufC, decW, decb, out, M);
}

// round 4
// speedup vs baseline: 1.6579x; 1.2911x over previous
#include <cuda_runtime.h>
#include <cstdint>

#define NNODES 50000
#define EDGES  800000
#define HDIM   256

// ---------------- scratch (no allocations allowed) ----------------
__device__ float g_bufA[NNODES * HDIM];
__device__ float g_bufB[NNODES * HDIM];
__device__ float g_bufC[NNODES * HDIM];
__device__ int   g_deg[NNODES];
__device__ float g_dinv[NNODES];
__device__ int   g_offs[NNODES + 1];
__device__ int   g_cur[NNODES];
__device__ int   g_bsum[256];
__device__ int   g_csr_src[EDGES];
__device__ float g_csr_w[EDGES];

// ---------------- degree / dinv ----------------
__global__ void deg_zero_kernel(int* __restrict__ deg, int n) {
    int i = blockIdx.x * blockDim.x + threadIdx.x;
    if (i < n) deg[i] = 0;
}

__global__ void deg_count_kernel(int* __restrict__ deg, const int* __restrict__ dst, int E) {
    int e = blockIdx.x * blockDim.x + threadIdx.x;
    if (e < E) atomicAdd(&deg[dst[e]], 1);
}

__global__ void dinv_kernel(float* __restrict__ dinv, const int* __restrict__ deg, int n) {
    int i = blockIdx.x * blockDim.x + threadIdx.x;
    if (i < n) dinv[i] = rsqrtf((float)(deg[i] + 1));  // +1 self-loop
}

// ---------------- 3-pass scan (multi-block) ----------------
__global__ void scan1_kernel(const int* __restrict__ deg, int* __restrict__ offs,
                             int* __restrict__ bsum, int n)
{
    __shared__ int sh[256];
    const int t = threadIdx.x;
    const int i = blockIdx.x * 256 + t;
    int v = (i < n) ? deg[i] : 0;
    sh[t] = v;
    __syncthreads();
#pragma unroll
    for (int off = 1; off < 256; off <<= 1) {
        int x = (t >= off) ? sh[t - off] : 0;
        __syncthreads();
        sh[t] += x;
        __syncthreads();
    }
    if (i < n) offs[i] = sh[t] - v;       // local exclusive
    if (t == 255) bsum[blockIdx.x] = sh[255];
}

__global__ void scan2_kernel(int* __restrict__ bsum, int* __restrict__ offs, int nb, int n)
{
    __shared__ int sh[256];
    const int t = threadIdx.x;
    int v = (t < nb) ? bsum[t] : 0;
    sh[t] = v;
    __syncthreads();
#pragma unroll
    for (int off = 1; off < 256; off <<= 1) {
        int x = (t >= off) ? sh[t - off] : 0;
        __syncthreads();
        sh[t] += x;
        __syncthreads();
    }
    if (t < nb) bsum[t] = sh[t] - v;      // exclusive block offsets
    if (t == 255) offs[n] = sh[255];      // total = E
}

__global__ void scan3_kernel(int* __restrict__ offs, int* __restrict__ cur,
                             const int* __restrict__ bsum, int n)
{
    int i = blockIdx.x * blockDim.x + threadIdx.x;
    if (i < n) {
        int o = offs[i] + bsum[i >> 8];
        offs[i] = o;
        cur[i]  = o;
    }
}

// ---------------- CSR fill (w fused) ----------------
__global__ void csr_fill_kernel(int* __restrict__ cur, int* __restrict__ csr_src,
                                float* __restrict__ csr_w,
                                const int* __restrict__ src, const int* __restrict__ dst,
                                const float* __restrict__ dinv, int E)
{
    int e = blockIdx.x * blockDim.x + threadIdx.x;
    if (e >= E) return;
    int s = src[e];
    int p = atomicAdd(&cur[dst[e]], 1);
    csr_src[p] = s;
    csr_w[p]   = dinv[s];
}

// ---------------- tf32x3 tensor-core SGEMM ----------------
// C[M,256] = A[M,K] @ W[K,256] (+bias), fp32-accuracy via tf32 hi/lo split.
// Tile 128x64, BK=8, 256 threads = 8 warps (4x2), warp tile 32x32.
// mma.sync.aligned.m16n8k8.row.col.f32.tf32.tf32.f32

__device__ __forceinline__ uint32_t f2tf32(float x) {
    uint32_t r;
    asm("cvt.rna.tf32.f32 %0, %1;" : "=r"(r) : "f"(x));
    return r;
}

__device__ __forceinline__ void mma_tf32(float* c, const uint32_t* a, const uint32_t* b) {
    asm volatile("mma.sync.aligned.m16n8k8.row.col.f32.tf32.tf32.f32 "
        "{%0,%1,%2,%3}, {%4,%5,%6,%7}, {%8,%9}, {%0,%1,%2,%3};"
        : "+f"(c[0]), "+f"(c[1]), "+f"(c[2]), "+f"(c[3])
        : "r"(a[0]), "r"(a[1]), "r"(a[2]), "r"(a[3]), "r"(b[0]), "r"(b[1]));
}

template <int K, bool BIAS, bool RELU_A>
__global__ void __launch_bounds__(256) gemm_tf32x3_kernel(
    const float* __restrict__ A, const float* __restrict__ W,
    const float* __restrict__ bias, float* __restrict__ C, int M)
{
    // [buf][hi=0/lo=1][k][row-or-col], padded so LDS row-stride ≡ 8 (mod 32) -> conflict-free frags
    __shared__ uint32_t sA[2][2][8][136];
    __shared__ uint32_t sB[2][2][8][72];

    const int tid  = threadIdx.x;
    const int lane = tid & 31;
    const int wid  = tid >> 5;
    const int wm   = wid >> 1;          // 0..3  (m 32-group)
    const int wn   = wid & 1;           // 0..1  (n 32-group)
    const int g    = lane >> 2;         // groupID 0..7
    const int tg   = lane & 3;          // thread-in-group 0..3
    const int row0 = blockIdx.x * 128;
    const int col0 = blockIdx.y * 64;

    // A loader: row = tid>>1 (0..127), k quad = (tid&1)*4
    const int ar  = tid >> 1;
    const int akq = (tid & 1) * 4;
    // B loader: k = tid>>5 (0..7), n pair = lane*2
    const int bkr = tid >> 5;
    const int bn2 = lane * 2;

    const int arow = row0 + ar;
    const bool a_ok = (arow < M);
    const float* Aptr = A + (size_t)arow * K + akq;
    const float* Wptr = W + (size_t)bkr * HDIM + col0 + bn2;

    float acc[2][4][4];
#pragma unroll
    for (int mt = 0; mt < 2; mt++)
#pragma unroll
        for (int nt = 0; nt < 4; nt++)
#pragma unroll
            for (int r = 0; r < 4; r++) acc[mt][nt][r] = 0.f;

    const int NT = K / 8;

    float4 av = make_float4(0.f, 0.f, 0.f, 0.f);
    if (a_ok) av = *(const float4*)Aptr;
    float2 bw = *(const float2*)Wptr;

    // stage store (split into tf32 hi/lo)
    auto stageStore = [&](int b, float4 v, float2 w) {
        float f[4] = {v.x, v.y, v.z, v.w};
#pragma unroll
        for (int j = 0; j < 4; j++) {
            float x = f[j];
            if (RELU_A) x = fmaxf(x, 0.f);
            uint32_t h = f2tf32(x);
            float lo = x - __uint_as_float(h);
            sA[b][0][akq + j][ar] = h;
            sA[b][1][akq + j][ar] = f2tf32(lo);
        }
        uint32_t hh[2], ll[2];
        float gg[2] = {w.x, w.y};
#pragma unroll
        for (int j = 0; j < 2; j++) {
            uint32_t h = f2tf32(gg[j]);
            float lo = gg[j] - __uint_as_float(h);
            hh[j] = h; ll[j] = f2tf32(lo);
        }
        *(uint2*)&sB[b][0][bkr][bn2] = make_uint2(hh[0], hh[1]);
        *(uint2*)&sB[b][1][bkr][bn2] = make_uint2(ll[0], ll[1]);
    };

    stageStore(0, av, bw);
    __syncthreads();

    for (int it = 0; it < NT; it++) {
        const int buf = it & 1;
        if (it + 1 < NT) {
            if (a_ok) av = *(const float4*)(Aptr + (it + 1) * 8);
            bw = *(const float2*)(Wptr + (size_t)(it + 1) * 8 * HDIM);
        }

        // load A fragments (hi/lo)
        uint32_t Ah[2][4], Al[2][4];
#pragma unroll
        for (int mt = 0; mt < 2; mt++) {
            int r = wm * 32 + mt * 16 + g;
            Ah[mt][0] = sA[buf][0][tg][r];       Al[mt][0] = sA[buf][1][tg][r];
            Ah[mt][1] = sA[buf][0][tg][r + 8];   Al[mt][1] = sA[buf][1][tg][r + 8];
            Ah[mt][2] = sA[buf][0][tg + 4][r];   Al[mt][2] = sA[buf][1][tg + 4][r];
            Ah[mt][3] = sA[buf][0][tg + 4][r + 8]; Al[mt][3] = sA[buf][1][tg + 4][r + 8];
        }
#pragma unroll
        for (int nt = 0; nt < 4; nt++) {
            int n = wn * 32 + nt * 8 + g;
            uint32_t Bh[2], Bl[2];
            Bh[0] = sB[buf][0][tg][n];     Bl[0] = sB[buf][1][tg][n];
            Bh[1] = sB[buf][0][tg + 4][n]; Bl[1] = sB[buf][1][tg + 4][n];
#pragma unroll
            for (int mt = 0; mt < 2; mt++) {
                mma_tf32(acc[mt][nt], Ah[mt], Bh);   // hi*hi
                mma_tf32(acc[mt][nt], Ah[mt], Bl);   // hi*lo
                mma_tf32(acc[mt][nt], Al[mt], Bh);   // lo*hi
            }
        }

        if (it + 1 < NT) {
            stageStore(buf ^ 1, av, bw);
            __syncthreads();
        }
    }

    // epilogue
#pragma unroll
    for (int mt = 0; mt < 2; mt++) {
#pragma unroll
        for (int nt = 0; nt < 4; nt++) {
            int r = row0 + wm * 32 + mt * 16 + g;
            int c = col0 + wn * 32 + nt * 8 + tg * 2;
            float2 v0 = {acc[mt][nt][0], acc[mt][nt][1]};
            float2 v1 = {acc[mt][nt][2], acc[mt][nt][3]};
            if (BIAS) {
                float b0 = bias[c], b1 = bias[c + 1];
                v0.x += b0; v0.y += b1;
                v1.x += b0; v1.y += b1;
            }
            if (r < M)     *(float2*)(C + (size_t)r * HDIM + c) = v0;
            if (r + 8 < M) *(float2*)(C + (size_t)(r + 8) * HDIM + c) = v1;
        }
    }
}

// ---------------- gather conv: out[d] = (Σ_in hw[s]·dinv[s])·dinv[d] + hw[d]·dinv[d]² + bias ----------------
__global__ void __launch_bounds__(256) gather_kernel(
    float* __restrict__ out, const float* __restrict__ hw,
    const int* __restrict__ offs, const int* __restrict__ csr_src,
    const float* __restrict__ csr_w, const float* __restrict__ dinv,
    const float* __restrict__ bias, int M)
{
    const int gw   = blockIdx.x * (blockDim.x >> 5) + (threadIdx.x >> 5);
    const int node = gw >> 1;
    if (node >= M) return;
    const int lane = threadIdx.x & 31;
    const int col  = (gw & 1) * 128 + lane * 4;

    const int beg = offs[node];
    const int end = offs[node + 1];

    float4 acc = make_float4(0.f, 0.f, 0.f, 0.f);
    int j = beg;
    for (; j + 1 < end; j += 2) {
        int s0 = csr_src[j], s1 = csr_src[j + 1];
        float w0 = csr_w[j], w1 = csr_w[j + 1];
        float4 v0 = *(const float4*)(hw + (size_t)s0 * HDIM + col);
        float4 v1 = *(const float4*)(hw + (size_t)s1 * HDIM + col);
        acc.x = fmaf(w0, v0.x, acc.x); acc.y = fmaf(w0, v0.y, acc.y);
        acc.z = fmaf(w0, v0.z, acc.z); acc.w = fmaf(w0, v0.w, acc.w);
        acc.x = fmaf(w1, v1.x, acc.x); acc.y = fmaf(w1, v1.y, acc.y);
        acc.z = fmaf(w1, v1.z, acc.z); acc.w = fmaf(w1, v1.w, acc.w);
    }
    if (j < end) {
        int s0 = csr_src[j];
        float w0 = csr_w[j];
        float4 v0 = *(const float4*)(hw + (size_t)s0 * HDIM + col);
        acc.x = fmaf(w0, v0.x, acc.x); acc.y = fmaf(w0, v0.y, acc.y);
        acc.z = fmaf(w0, v0.z, acc.z); acc.w = fmaf(w0, v0.w, acc.w);
    }

    const float dd = dinv[node];
    const float ds = dd * dd;
    float4 self = *(const float4*)(hw + (size_t)node * HDIM + col);
    float4 bb   = *(const float4*)(bias + col);
    float4 o;
    o.x = fmaf(acc.x, dd, fmaf(self.x, ds, bb.x));
    o.y = fmaf(acc.y, dd, fmaf(self.y, ds, bb.y));
    o.z = fmaf(acc.z, dd, fmaf(self.z, ds, bb.z));
    o.w = fmaf(acc.w, dd, fmaf(self.w, ds, bb.w));
    *(float4*)(out + (size_t)node * HDIM + col) = o;
}

// ---------------- decoder: out[i] = relu(h[i,:]) . dec_W + dec_b ----------------
__global__ void __launch_bounds__(256) decoder_kernel(
    const float* __restrict__ h, const float* __restrict__ dw,
    const float* __restrict__ db, float* __restrict__ out, int M)
{
    int row  = blockIdx.x * (blockDim.x >> 5) + (threadIdx.x >> 5);
    int lane = threadIdx.x & 31;
    if (row >= M) return;
    const float* hr = h + (size_t)row * HDIM;
    float s = 0.f;
#pragma unroll
    for (int i = 0; i < 8; i++) {
        float v = fmaxf(hr[lane + i * 32], 0.f);
        s = fmaf(v, __ldg(&dw[lane + i * 32]), s);
    }
#pragma unroll
    for (int o = 16; o > 0; o >>= 1) s += __shfl_xor_sync(0xffffffffu, s, o);
    if (lane == 0) out[row] = s + db[0];
}

// ---------------- launch ----------------
extern "C" void kernel_launch(void* const* d_in, const int* in_sizes, int n_in,
                              void* d_out, int out_size)
{
    const float* x     = (const float*)d_in[0];
    const int*   ei    = (const int*)d_in[1];
    const float* enc_W = (const float*)d_in[2];
    const float* enc_b = (const float*)d_in[3];
    const float* W1    = (const float*)d_in[4];
    const float* b1    = (const float*)d_in[5];
    const float* W2    = (const float*)d_in[6];
    const float* b2    = (const float*)d_in[7];
    const float* W3    = (const float*)d_in[8];
    const float* b3    = (const float*)d_in[9];
    const float* decW  = (const float*)d_in[10];
    const float* decb  = (const float*)d_in[11];
    float* out = (float*)d_out;

    const int M = in_sizes[0] / 128;   // 50000
    const int E = in_sizes[1] / 2;     // 800000
    const int* src = ei;
    const int* dst = ei + E;

    float *bufA, *bufB, *bufC, *dinv, *csr_w;
    int *deg, *offs, *cur, *bsum, *csr_src;
    cudaGetSymbolAddress((void**)&bufA,    g_bufA);
    cudaGetSymbolAddress((void**)&bufB,    g_bufB);
    cudaGetSymbolAddress((void**)&bufC,    g_bufC);
    cudaGetSymbolAddress((void**)&deg,     g_deg);
    cudaGetSymbolAddress((void**)&dinv,    g_dinv);
    cudaGetSymbolAddress((void**)&offs,    g_offs);
    cudaGetSymbolAddress((void**)&cur,     g_cur);
    cudaGetSymbolAddress((void**)&bsum,    g_bsum);
    cudaGetSymbolAddress((void**)&csr_src, g_csr_src);
    cudaGetSymbolAddress((void**)&csr_w,   g_csr_w);

    const int nb = (M + 255) / 256;    // scan blocks (196)

    // ---- graph preprocessing (once per call, reused by 3 convs) ----
    deg_zero_kernel<<<nb, 256>>>(deg, M);
    deg_count_kernel<<<(E + 255) / 256, 256>>>(deg, dst, E);
    dinv_kernel<<<nb, 256>>>(dinv, deg, M);
    scan1_kernel<<<nb, 256>>>(deg, offs, bsum, M);
    scan2_kernel<<<1, 256>>>(bsum, offs, nb, M);
    scan3_kernel<<<nb, 256>>>(offs, cur, bsum, M);
    csr_fill_kernel<<<(E + 255) / 256, 256>>>(cur, csr_src, csr_w, src, dst, dinv, E);

    const dim3 ggrid((M + 127) / 128, HDIM / 64);
    const int gat_blocks = (2 * M + 7) / 8;

    // encoder: bufA = x @ enc_W + enc_b
    gemm_tf32x3_kernel<128, true, false><<<ggrid, 256>>>(x, enc_W, enc_b, bufA, M);

    // conv1
    gemm_tf32x3_kernel<256, false, false><<<ggrid, 256>>>(bufA, W1, nullptr, bufB, M);
    gather_kernel<<<gat_blocks, 256>>>(bufC, bufB, offs, csr_src, csr_w, dinv, b1, M);

    // conv2 (relu fused into GEMM A-load)
    gemm_tf32x3_kernel<256, false, true><<<ggrid, 256>>>(bufC, W2, nullptr, bufB, M);
    gather_kernel<<<gat_blocks, 256>>>(bufA, bufB, offs, csr_src, csr_w, dinv, b2, M);

    // conv3
    gemm_tf32x3_kernel<256, false, true><<<ggrid, 256>>>(bufA, W3, nullptr, bufB, M);
    gather_kernel<<<gat_blocks, 256>>>(bufC, bufB, offs, csr_src, csr_w, dinv, b3, M);

    // decoder (relu fused)
    decoder_kernel<<<(M + 7) / 8, 256>>>(bufC, decW, decb, out, M);
}

// round 5
// speedup vs baseline: 2.2444x; 1.3537x over previous
#include <cuda_runtime.h>
#include <cuda_fp16.h>
#include <cstdint>

#define NNODES 50000
#define EDGES  800000
#define HDIM   256

// ---------------- scratch (no allocations allowed) ----------------
__device__ float  g_bufA[NNODES * HDIM];
__device__ float  g_bufB[NNODES * HDIM];
__device__ __half g_hwh[NNODES * HDIM];
__device__ __half g_Wh[4][65536];
__device__ __half g_Wl[4][65536];
__device__ int    g_deg[NNODES];
__device__ float  g_dinv[NNODES];
__device__ int    g_offs[NNODES + 1];
__device__ int    g_cur[NNODES];
__device__ int    g_bsum[256];
__device__ int    g_csr_src[EDGES];
__device__ float  g_csr_w[EDGES];

// ---------------- degree / dinv ----------------
__global__ void deg_zero_kernel(int* __restrict__ deg, int n) {
    int i = blockIdx.x * blockDim.x + threadIdx.x;
    if (i < n) deg[i] = 0;
}

__global__ void deg_count_kernel(int* __restrict__ deg, const int* __restrict__ dst, int E) {
    int e = blockIdx.x * blockDim.x + threadIdx.x;
    if (e < E) atomicAdd(&deg[dst[e]], 1);
}

__global__ void dinv_kernel(float* __restrict__ dinv, const int* __restrict__ deg, int n) {
    int i = blockIdx.x * blockDim.x + threadIdx.x;
    if (i < n) dinv[i] = rsqrtf((float)(deg[i] + 1));  // +1 self-loop
}

// ---------------- 3-pass scan (multi-block) ----------------
__global__ void scan1_kernel(const int* __restrict__ deg, int* __restrict__ offs,
                             int* __restrict__ bsum, int n)
{
    __shared__ int sh[256];
    const int t = threadIdx.x;
    const int i = blockIdx.x * 256 + t;
    int v = (i < n) ? deg[i] : 0;
    sh[t] = v;
    __syncthreads();
#pragma unroll
    for (int off = 1; off < 256; off <<= 1) {
        int x = (t >= off) ? sh[t - off] : 0;
        __syncthreads();
        sh[t] += x;
        __syncthreads();
    }
    if (i < n) offs[i] = sh[t] - v;
    if (t == 255) bsum[blockIdx.x] = sh[255];
}

__global__ void scan2_kernel(int* __restrict__ bsum, int* __restrict__ offs, int nb, int n)
{
    __shared__ int sh[256];
    const int t = threadIdx.x;
    int v = (t < nb) ? bsum[t] : 0;
    sh[t] = v;
    __syncthreads();
#pragma unroll
    for (int off = 1; off < 256; off <<= 1) {
        int x = (t >= off) ? sh[t - off] : 0;
        __syncthreads();
        sh[t] += x;
        __syncthreads();
    }
    if (t < nb) bsum[t] = sh[t] - v;
    if (t == 255) offs[n] = sh[255];
}

__global__ void scan3_kernel(int* __restrict__ offs, int* __restrict__ cur,
                             const int* __restrict__ bsum, int n)
{
    int i = blockIdx.x * blockDim.x + threadIdx.x;
    if (i < n) {
        int o = offs[i] + bsum[i >> 8];
        offs[i] = o;
        cur[i]  = o;
    }
}

// ---------------- CSR fill (w fused) ----------------
__global__ void csr_fill_kernel(int* __restrict__ cur, int* __restrict__ csr_src,
                                float* __restrict__ csr_w,
                                const int* __restrict__ src, const int* __restrict__ dst,
                                const float* __restrict__ dinv, int E)
{
    int e = blockIdx.x * blockDim.x + threadIdx.x;
    if (e >= E) return;
    int s = src[e];
    int p = atomicAdd(&cur[dst[e]], 1);
    csr_src[p] = s;
    csr_w[p]   = dinv[s];
}

// ---------------- weight transpose + fp16 hi/lo split (once per layer) ----------------
// W[k][256] fp32 -> Wt_h[n][K], Wt_l[n][K] halves (n-major, k contiguous)
__global__ void wsplit_kernel(const float* __restrict__ W, __half* __restrict__ Wh,
                              __half* __restrict__ Wl, int K)
{
    int idx = blockIdx.x * 256 + threadIdx.x;   // idx = n*K + k (k fastest)
    if (idx >= 256 * K) return;
    int n = idx / K, k = idx - n * K;
    float x = W[k * 256 + n];
    __half h = __float2half_rn(x);
    float lo = x - __half2float(h);
    Wh[idx] = h;
    Wl[idx] = __float2half_rn(lo);
}

// ---------------- fp16x3 tensor-core GEMM ----------------
// C[M,256] = A[M,K] @ W[K,256] (+bias), ~fp32 accuracy via fp16 hi/lo split:
// acc += Ah*Bh + Ah*Bl + Al*Bh   (lo*lo term ~2^-24, dropped)
// Tile 128x128, BK=16, 256 threads = 8 warps (4m x 2n), warp tile 32x64.
// mma.sync.aligned.m16n8k16.row.col.f32.f16.f16.f32

__device__ __forceinline__ void mma_f16(float* c, const uint32_t* a, uint32_t b0, uint32_t b1) {
    asm volatile("mma.sync.aligned.m16n8k16.row.col.f32.f16.f16.f32 "
        "{%0,%1,%2,%3}, {%4,%5,%6,%7}, {%8,%9}, {%0,%1,%2,%3};"
        : "+f"(c[0]), "+f"(c[1]), "+f"(c[2]), "+f"(c[3])
        : "r"(a[0]), "r"(a[1]), "r"(a[2]), "r"(a[3]), "r"(b0), "r"(b1));
}

template <int K, bool BIAS, bool RELU_A, bool OUTH>
__global__ void __launch_bounds__(256) gemm_f16x3_kernel(
    const float* __restrict__ A, const __half* __restrict__ Wh,
    const __half* __restrict__ Wl, const float* __restrict__ bias,
    void* __restrict__ Cout, int M)
{
    // [buf][plane hi=0/lo=1][row-or-n][k(16)+pad(8)]  -> 24KB each, 48KB total
    __shared__ __half sA[2][2][128][24];
    __shared__ __half sB[2][2][128][24];

    const int tid  = threadIdx.x;
    const int lane = tid & 31;
    const int wid  = tid >> 5;
    const int wm   = wid >> 1;           // 0..3 (m 32-group)
    const int wn   = wid & 1;            // 0..1 (n 64-group)
    const int g    = lane >> 2;          // 0..7
    const int tg   = lane & 3;           // 0..3
    const int row0 = blockIdx.x * 128;
    const int col0 = blockIdx.y * 128;

    // A loader: row = tid>>1 (0..127), k-octet = (tid&1)*8
    const int ar  = tid >> 1;
    const int ak8 = (tid & 1) * 8;
    // B loader: n = tid&127, k-octet = (tid>>7)*8
    const int bn  = tid & 127;
    const int bh8 = (tid >> 7) * 8;

    const int arow = row0 + ar;
    const bool a_ok = (arow < M);
    const float*  Aptr = A + (size_t)arow * K + ak8;
    const __half* Bph  = Wh + (size_t)(col0 + bn) * K + bh8;
    const __half* Bpl  = Wl + (size_t)(col0 + bn) * K + bh8;

    float acc[2][8][4];
#pragma unroll
    for (int mt = 0; mt < 2; mt++)
#pragma unroll
        for (int nt = 0; nt < 8; nt++)
#pragma unroll
            for (int r = 0; r < 4; r++) acc[mt][nt][r] = 0.f;

    const int NT = K / 16;

    float4 av0 = make_float4(0.f, 0.f, 0.f, 0.f), av1 = av0;
    uint4 bvh, bvl;

    // prefetch stage 0
    if (a_ok) { av0 = *(const float4*)Aptr; av1 = *(const float4*)(Aptr + 4); }
    bvh = *(const uint4*)Bph;
    bvl = *(const uint4*)Bpl;

    auto stageStore = [&](int b) {
        float f[8] = {av0.x, av0.y, av0.z, av0.w, av1.x, av1.y, av1.z, av1.w};
        __half hb[8], lb[8];
#pragma unroll
        for (int j = 0; j < 8; j++) {
            float x = f[j];
            if (RELU_A) x = fmaxf(x, 0.f);
            __half h = __float2half_rn(x);
            hb[j] = h;
            lb[j] = __float2half_rn(x - __half2float(h));
        }
        *(uint4*)&sA[b][0][ar][ak8] = *(const uint4*)hb;
        *(uint4*)&sA[b][1][ar][ak8] = *(const uint4*)lb;
        *(uint4*)&sB[b][0][bn][bh8] = bvh;
        *(uint4*)&sB[b][1][bn][bh8] = bvl;
    };

    stageStore(0);
    __syncthreads();

    for (int it = 0; it < NT; it++) {
        const int buf = it & 1;
        if (it + 1 < NT) {
            const int off = (it + 1) * 16;
            if (a_ok) { av0 = *(const float4*)(Aptr + off); av1 = *(const float4*)(Aptr + off + 4); }
            bvh = *(const uint4*)(Bph + off);
            bvl = *(const uint4*)(Bpl + off);
        }

        // A fragments (hi/lo)
        uint32_t Ah[2][4], Al[2][4];
#pragma unroll
        for (int mt = 0; mt < 2; mt++) {
            int r = wm * 32 + mt * 16 + g;
            Ah[mt][0] = *(const uint32_t*)&sA[buf][0][r][2 * tg];
            Ah[mt][1] = *(const uint32_t*)&sA[buf][0][r + 8][2 * tg];
            Ah[mt][2] = *(const uint32_t*)&sA[buf][0][r][2 * tg + 8];
            Ah[mt][3] = *(const uint32_t*)&sA[buf][0][r + 8][2 * tg + 8];
            Al[mt][0] = *(const uint32_t*)&sA[buf][1][r][2 * tg];
            Al[mt][1] = *(const uint32_t*)&sA[buf][1][r + 8][2 * tg];
            Al[mt][2] = *(const uint32_t*)&sA[buf][1][r][2 * tg + 8];
            Al[mt][3] = *(const uint32_t*)&sA[buf][1][r + 8][2 * tg + 8];
        }
#pragma unroll
        for (int nt = 0; nt < 8; nt++) {
            int n = wn * 64 + nt * 8 + g;
            uint32_t bh0 = *(const uint32_t*)&sB[buf][0][n][2 * tg];
            uint32_t bh1 = *(const uint32_t*)&sB[buf][0][n][2 * tg + 8];
            uint32_t bl0 = *(const uint32_t*)&sB[buf][1][n][2 * tg];
            uint32_t bl1 = *(const uint32_t*)&sB[buf][1][n][2 * tg + 8];
#pragma unroll
            for (int mt = 0; mt < 2; mt++) {
                mma_f16(acc[mt][nt], Ah[mt], bh0, bh1);   // hi*hi
                mma_f16(acc[mt][nt], Ah[mt], bl0, bl1);   // hi*lo
                mma_f16(acc[mt][nt], Al[mt], bh0, bh1);   // lo*hi
            }
        }

        if (it + 1 < NT) {
            stageStore(buf ^ 1);
            __syncthreads();
        }
    }

    // epilogue
#pragma unroll
    for (int mt = 0; mt < 2; mt++) {
#pragma unroll
        for (int nt = 0; nt < 8; nt++) {
            int r = row0 + wm * 32 + mt * 16 + g;
            int c = col0 + wn * 64 + nt * 8 + 2 * tg;
            float c0 = acc[mt][nt][0], c1 = acc[mt][nt][1];
            float c2 = acc[mt][nt][2], c3 = acc[mt][nt][3];
            if (BIAS) {
                float b0 = bias[c], b1 = bias[c + 1];
                c0 += b0; c1 += b1; c2 += b0; c3 += b1;
            }
            if (OUTH) {
                __half* C16 = (__half*)Cout;
                if (r < M)     *(__half2*)(C16 + (size_t)r * HDIM + c)       = __floats2half2_rn(c0, c1);
                if (r + 8 < M) *(__half2*)(C16 + (size_t)(r + 8) * HDIM + c) = __floats2half2_rn(c2, c3);
            } else {
                float* C32 = (float*)Cout;
                if (r < M)     { float2 v = {c0, c1}; *(float2*)(C32 + (size_t)r * HDIM + c) = v; }
                if (r + 8 < M) { float2 v = {c2, c3}; *(float2*)(C32 + (size_t)(r + 8) * HDIM + c) = v; }
            }
        }
    }
}

// ---------------- gather conv (fp16 input): out = (Σ hw[s]·w)·dinv[d] + hw[d]·dinv[d]² + bias ----------------
// 1 warp per node; lane handles 8 cols (one LDG.128 of 8 halves per edge).
__global__ void __launch_bounds__(256) gather_kernel(
    float* __restrict__ out, const __half* __restrict__ hw,
    const int* __restrict__ offs, const int* __restrict__ csr_src,
    const float* __restrict__ csr_w, const float* __restrict__ dinv,
    const float* __restrict__ bias, int M)
{
    const int node = blockIdx.x * 8 + (threadIdx.x >> 5);
    if (node >= M) return;
    const int lane = threadIdx.x & 31;
    const int col  = lane * 8;

    const int beg = offs[node];
    const int end = offs[node + 1];

    float acc[8];
#pragma unroll
    for (int i = 0; i < 8; i++) acc[i] = 0.f;

    auto accum = [&](uint4 u, float w) {
        float2 p0 = __half22float2(*(const __half2*)&u.x);
        float2 p1 = __half22float2(*(const __half2*)&u.y);
        float2 p2 = __half22float2(*(const __half2*)&u.z);
        float2 p3 = __half22float2(*(const __half2*)&u.w);
        acc[0] = fmaf(w, p0.x, acc[0]); acc[1] = fmaf(w, p0.y, acc[1]);
        acc[2] = fmaf(w, p1.x, acc[2]); acc[3] = fmaf(w, p1.y, acc[3]);
        acc[4] = fmaf(w, p2.x, acc[4]); acc[5] = fmaf(w, p2.y, acc[5]);
        acc[6] = fmaf(w, p3.x, acc[6]); acc[7] = fmaf(w, p3.y, acc[7]);
    };

    int j = beg;
    for (; j + 1 < end; j += 2) {
        int s0 = csr_src[j], s1 = csr_src[j + 1];
        float w0 = csr_w[j], w1 = csr_w[j + 1];
        uint4 u0 = *(const uint4*)(hw + (size_t)s0 * HDIM + col);
        uint4 u1 = *(const uint4*)(hw + (size_t)s1 * HDIM + col);
        accum(u0, w0);
        accum(u1, w1);
    }
    if (j < end) {
        uint4 u0 = *(const uint4*)(hw + (size_t)csr_src[j] * HDIM + col);
        accum(u0, csr_w[j]);
    }

    const float dd = dinv[node];
    const float ds = dd * dd;
    uint4 su = *(const uint4*)(hw + (size_t)node * HDIM + col);
    float2 s0 = __half22float2(*(const __half2*)&su.x);
    float2 s1 = __half22float2(*(const __half2*)&su.y);
    float2 s2 = __half22float2(*(const __half2*)&su.z);
    float2 s3 = __half22float2(*(const __half2*)&su.w);
    float sf[8] = {s0.x, s0.y, s1.x, s1.y, s2.x, s2.y, s3.x, s3.y};

    float4 bb0 = *(const float4*)(bias + col);
    float4 bb1 = *(const float4*)(bias + col + 4);
    float bf[8] = {bb0.x, bb0.y, bb0.z, bb0.w, bb1.x, bb1.y, bb1.z, bb1.w};

    float o[8];
#pragma unroll
    for (int i = 0; i < 8; i++)
        o[i] = fmaf(acc[i], dd, fmaf(sf[i], ds, bf[i]));

    float* op = out + (size_t)node * HDIM + col;
    *(float4*)op       = make_float4(o[0], o[1], o[2], o[3]);
    *(float4*)(op + 4) = make_float4(o[4], o[5], o[6], o[7]);
}

// ---------------- decoder: out[i] = relu(h[i,:]) . dec_W + dec_b ----------------
__global__ void __launch_bounds__(256) decoder_kernel(
    const float* __restrict__ h, const float* __restrict__ dw,
    const float* __restrict__ db, float* __restrict__ out, int M)
{
    int row  = blockIdx.x * (blockDim.x >> 5) + (threadIdx.x >> 5);
    int lane = threadIdx.x & 31;
    if (row >= M) return;
    const float* hr = h + (size_t)row * HDIM;
    float s = 0.f;
#pragma unroll
    for (int i = 0; i < 8; i++) {
        float v = fmaxf(hr[lane + i * 32], 0.f);
        s = fmaf(v, __ldg(&dw[lane + i * 32]), s);
    }
#pragma unroll
    for (int o = 16; o > 0; o >>= 1) s += __shfl_xor_sync(0xffffffffu, s, o);
    if (lane == 0) out[row] = s + db[0];
}

// ---------------- launch ----------------
extern "C" void kernel_launch(void* const* d_in, const int* in_sizes, int n_in,
                              void* d_out, int out_size)
{
    const float* x     = (const float*)d_in[0];
    const int*   ei    = (const int*)d_in[1];
    const float* enc_W = (const float*)d_in[2];
    const float* enc_b = (const float*)d_in[3];
    const float* W1    = (const float*)d_in[4];
    const float* b1    = (const float*)d_in[5];
    const float* W2    = (const float*)d_in[6];
    const float* b2    = (const float*)d_in[7];
    const float* W3    = (const float*)d_in[8];
    const float* b3    = (const float*)d_in[9];
    const float* decW  = (const float*)d_in[10];
    const float* decb  = (const float*)d_in[11];
    float* out = (float*)d_out;

    const int M = in_sizes[0] / 128;   // 50000
    const int E = in_sizes[1] / 2;     // 800000
    const int* src = ei;
    const int* dst = ei + E;

    float *bufA, *bufB, *dinv, *csr_w;
    __half *hwh, *WhBase, *WlBase;
    int *deg, *offs, *cur, *bsum, *csr_src;
    cudaGetSymbolAddress((void**)&bufA,    g_bufA);
    cudaGetSymbolAddress((void**)&bufB,    g_bufB);
    cudaGetSymbolAddress((void**)&hwh,     g_hwh);
    cudaGetSymbolAddress((void**)&WhBase,  g_Wh);
    cudaGetSymbolAddress((void**)&WlBase,  g_Wl);
    cudaGetSymbolAddress((void**)&deg,     g_deg);
    cudaGetSymbolAddress((void**)&dinv,    g_dinv);
    cudaGetSymbolAddress((void**)&offs,    g_offs);
    cudaGetSymbolAddress((void**)&cur,     g_cur);
    cudaGetSymbolAddress((void**)&bsum,    g_bsum);
    cudaGetSymbolAddress((void**)&csr_src, g_csr_src);
    cudaGetSymbolAddress((void**)&csr_w,   g_csr_w);

    __half* Wh[4] = {WhBase, WhBase + 65536, WhBase + 2 * 65536, WhBase + 3 * 65536};
    __half* Wl[4] = {WlBase, WlBase + 65536, WlBase + 2 * 65536, WlBase + 3 * 65536};

    const int nb = (M + 255) / 256;

    // ---- graph preprocessing ----
    deg_zero_kernel<<<nb, 256>>>(deg, M);
    deg_count_kernel<<<(E + 255) / 256, 256>>>(deg, dst, E);
    dinv_kernel<<<nb, 256>>>(dinv, deg, M);
    scan1_kernel<<<nb, 256>>>(deg, offs, bsum, M);
    scan2_kernel<<<1, 256>>>(bsum, offs, nb, M);
    scan3_kernel<<<nb, 256>>>(offs, cur, bsum, M);
    csr_fill_kernel<<<(E + 255) / 256, 256>>>(cur, csr_src, csr_w, src, dst, dinv, E);

    // ---- weight transpose + split ----
    wsplit_kernel<<<(256 * 128 + 255) / 256, 256>>>(enc_W, Wh[0], Wl[0], 128);
    wsplit_kernel<<<(256 * 256 + 255) / 256, 256>>>(W1,    Wh[1], Wl[1], 256);
    wsplit_kernel<<<(256 * 256 + 255) / 256, 256>>>(W2,    Wh[2], Wl[2], 256);
    wsplit_kernel<<<(256 * 256 + 255) / 256, 256>>>(W3,    Wh[3], Wl[3], 256);

    const dim3 gg((M + 127) / 128, 2);
    const int gat_blocks = (M + 7) / 8;

    // encoder: bufA = x @ enc_W + enc_b  (fp32 out)
    gemm_f16x3_kernel<128, true, false, false><<<gg, 256>>>(x, Wh[0], Wl[0], enc_b, bufA, M);

    // conv1: hwh = bufA @ W1 (fp16 out); bufB = gather(hwh) + b1
    gemm_f16x3_kernel<256, false, false, true><<<gg, 256>>>(bufA, Wh[1], Wl[1], nullptr, hwh, M);
    gather_kernel<<<gat_blocks, 256>>>(bufB, hwh, offs, csr_src, csr_w, dinv, b1, M);

    // conv2 (relu fused into GEMM A-load)
    gemm_f16x3_kernel<256, false, true, true><<<gg, 256>>>(bufB, Wh[2], Wl[2], nullptr, hwh, M);
    gather_kernel<<<gat_blocks, 256>>>(bufA, hwh, offs, csr_src, csr_w, dinv, b2, M);

    // conv3
    gemm_f16x3_kernel<256, false, true, true><<<gg, 256>>>(bufA, Wh[3], Wl[3], nullptr, hwh, M);
    gather_kernel<<<gat_blocks, 256>>>(bufB, hwh, offs, csr_src, csr_w, dinv, b3, M);

    // decoder (relu fused)
    decoder_kernel<<<(M + 7) / 8, 256>>>(bufB, decW, decb, out, M);
}

// round 6
// speedup vs baseline: 2.5004x; 1.1141x over previous
#include <cuda_runtime.h>
#include <cuda_fp16.h>
#include <cstdint>

#define NNODES 50000
#define EDGES  800000
#define HDIM   256

// ---------------- scratch (no allocations allowed) ----------------
__device__ float  g_bufA[NNODES * HDIM];
__device__ float  g_bufB[NNODES * HDIM];
__device__ __half g_hwh[NNODES * HDIM];
__device__ __half g_Wh[4][65536];
__device__ __half g_Wl[4][65536];
__device__ int    g_deg[NNODES];
__device__ float  g_dinv[NNODES];
__device__ int    g_offs[NNODES + 1];
__device__ int    g_cur[NNODES];
__device__ int    g_bsum[256];
__device__ int    g_csr_src[EDGES];
__device__ float  g_csr_w[EDGES];

// ---------------- degree / dinv ----------------
__global__ void deg_zero_kernel(int* __restrict__ deg, int n) {
    int i = blockIdx.x * blockDim.x + threadIdx.x;
    if (i < n) deg[i] = 0;
}

__global__ void deg_count_kernel(int* __restrict__ deg, const int* __restrict__ dst, int E) {
    int e = blockIdx.x * blockDim.x + threadIdx.x;
    if (e < E) atomicAdd(&deg[dst[e]], 1);
}

__global__ void dinv_kernel(float* __restrict__ dinv, const int* __restrict__ deg, int n) {
    int i = blockIdx.x * blockDim.x + threadIdx.x;
    if (i < n) dinv[i] = rsqrtf((float)(deg[i] + 1));  // +1 self-loop
}

// ---------------- 3-pass scan (multi-block) ----------------
__global__ void scan1_kernel(const int* __restrict__ deg, int* __restrict__ offs,
                             int* __restrict__ bsum, int n)
{
    __shared__ int sh[256];
    const int t = threadIdx.x;
    const int i = blockIdx.x * 256 + t;
    int v = (i < n) ? deg[i] : 0;
    sh[t] = v;
    __syncthreads();
#pragma unroll
    for (int off = 1; off < 256; off <<= 1) {
        int x = (t >= off) ? sh[t - off] : 0;
        __syncthreads();
        sh[t] += x;
        __syncthreads();
    }
    if (i < n) offs[i] = sh[t] - v;
    if (t == 255) bsum[blockIdx.x] = sh[255];
}

__global__ void scan2_kernel(int* __restrict__ bsum, int* __restrict__ offs, int nb, int n)
{
    __shared__ int sh[256];
    const int t = threadIdx.x;
    int v = (t < nb) ? bsum[t] : 0;
    sh[t] = v;
    __syncthreads();
#pragma unroll
    for (int off = 1; off < 256; off <<= 1) {
        int x = (t >= off) ? sh[t - off] : 0;
        __syncthreads();
        sh[t] += x;
        __syncthreads();
    }
    if (t < nb) bsum[t] = sh[t] - v;
    if (t == 255) offs[n] = sh[255];
}

__global__ void scan3_kernel(int* __restrict__ offs, int* __restrict__ cur,
                             const int* __restrict__ bsum, int n)
{
    int i = blockIdx.x * blockDim.x + threadIdx.x;
    if (i < n) {
        int o = offs[i] + bsum[i >> 8];
        offs[i] = o;
        cur[i]  = o;
    }
}

// ---------------- CSR fill (w fused) ----------------
__global__ void csr_fill_kernel(int* __restrict__ cur, int* __restrict__ csr_src,
                                float* __restrict__ csr_w,
                                const int* __restrict__ src, const int* __restrict__ dst,
                                const float* __restrict__ dinv, int E)
{
    int e = blockIdx.x * blockDim.x + threadIdx.x;
    if (e >= E) return;
    int s = src[e];
    int p = atomicAdd(&cur[dst[e]], 1);
    csr_src[p] = s;
    csr_w[p]   = dinv[s];
}

// ---------------- weight transpose + fp16 hi/lo split (once per layer) ----------------
// W[k][256] fp32 -> Wt_h[n][K], Wt_l[n][K] halves (n-major, k contiguous)
__global__ void wsplit_kernel(const float* __restrict__ W, __half* __restrict__ Wh,
                              __half* __restrict__ Wl, int K)
{
    int idx = blockIdx.x * 256 + threadIdx.x;   // idx = n*K + k (k fastest)
    if (idx >= 256 * K) return;
    int n = idx / K, k = idx - n * K;
    float x = W[k * 256 + n];
    __half h = __float2half_rn(x);
    float lo = x - __half2float(h);
    Wh[idx] = h;
    Wl[idx] = __float2half_rn(lo);
}

// ---------------- fp16x2 tensor-core GEMM ----------------
// C[M,256] = A[M,K] @ W[K,256] (+bias):  acc += Ah*Bh + Ah*Bl
// (weight-lo correction kept — precomputed; activation-lo dropped, ~2^-12 rms rel err)
// Tile 128x128, BK=16, 256 threads = 8 warps (4m x 2n), warp tile 32x64.
// mma.sync.aligned.m16n8k16.row.col.f32.f16.f16.f32

__device__ __forceinline__ void mma_f16(float* c, const uint32_t* a, uint32_t b0, uint32_t b1) {
    asm volatile("mma.sync.aligned.m16n8k16.row.col.f32.f16.f16.f32 "
        "{%0,%1,%2,%3}, {%4,%5,%6,%7}, {%8,%9}, {%0,%1,%2,%3};"
        : "+f"(c[0]), "+f"(c[1]), "+f"(c[2]), "+f"(c[3])
        : "r"(a[0]), "r"(a[1]), "r"(a[2]), "r"(a[3]), "r"(b0), "r"(b1));
}

template <int K, bool BIAS, bool RELU_A, bool OUTH>
__global__ void __launch_bounds__(256) gemm_f16x2_kernel(
    const float* __restrict__ A, const __half* __restrict__ Wh,
    const __half* __restrict__ Wl, const float* __restrict__ bias,
    void* __restrict__ Cout, int M)
{
    // sA: [buf][row][k(16)+pad(8)] single plane (12KB)
    // sB: [buf][plane hi/lo][n][k+pad] (24KB)
    __shared__ __half sA[2][128][24];
    __shared__ __half sB[2][2][128][24];

    const int tid  = threadIdx.x;
    const int lane = tid & 31;
    const int wid  = tid >> 5;
    const int wm   = wid >> 1;           // 0..3 (m 32-group)
    const int wn   = wid & 1;            // 0..1 (n 64-group)
    const int g    = lane >> 2;          // 0..7
    const int tg   = lane & 3;           // 0..3
    const int row0 = blockIdx.x * 128;
    const int col0 = blockIdx.y * 128;

    // A loader: row = tid>>1 (0..127), k-octet = (tid&1)*8
    const int ar  = tid >> 1;
    const int ak8 = (tid & 1) * 8;
    // B loader: n = tid&127, k-octet = (tid>>7)*8
    const int bn  = tid & 127;
    const int bh8 = (tid >> 7) * 8;

    const int arow = row0 + ar;
    const bool a_ok = (arow < M);
    const float*  Aptr = A + (size_t)arow * K + ak8;
    const __half* Bph  = Wh + (size_t)(col0 + bn) * K + bh8;
    const __half* Bpl  = Wl + (size_t)(col0 + bn) * K + bh8;

    float acc[2][8][4];
#pragma unroll
    for (int mt = 0; mt < 2; mt++)
#pragma unroll
        for (int nt = 0; nt < 8; nt++)
#pragma unroll
            for (int r = 0; r < 4; r++) acc[mt][nt][r] = 0.f;

    const int NT = K / 16;

    float4 av0 = make_float4(0.f, 0.f, 0.f, 0.f), av1 = av0;
    uint4 bvh, bvl;

    // prefetch stage 0
    if (a_ok) { av0 = *(const float4*)Aptr; av1 = *(const float4*)(Aptr + 4); }
    bvh = *(const uint4*)Bph;
    bvl = *(const uint4*)Bpl;

    auto stageStore = [&](int b) {
        float f[8] = {av0.x, av0.y, av0.z, av0.w, av1.x, av1.y, av1.z, av1.w};
        __half hb[8];
#pragma unroll
        for (int j = 0; j < 8; j++) {
            float x = f[j];
            if (RELU_A) x = fmaxf(x, 0.f);
            hb[j] = __float2half_rn(x);
        }
        *(uint4*)&sA[b][ar][ak8]    = *(const uint4*)hb;
        *(uint4*)&sB[b][0][bn][bh8] = bvh;
        *(uint4*)&sB[b][1][bn][bh8] = bvl;
    };

    stageStore(0);
    __syncthreads();

    for (int it = 0; it < NT; it++) {
        const int buf = it & 1;
        if (it + 1 < NT) {
            const int off = (it + 1) * 16;
            if (a_ok) { av0 = *(const float4*)(Aptr + off); av1 = *(const float4*)(Aptr + off + 4); }
            bvh = *(const uint4*)(Bph + off);
            bvl = *(const uint4*)(Bpl + off);
        }

        // A fragments (single plane)
        uint32_t Ah[2][4];
#pragma unroll
        for (int mt = 0; mt < 2; mt++) {
            int r = wm * 32 + mt * 16 + g;
            Ah[mt][0] = *(const uint32_t*)&sA[buf][r][2 * tg];
            Ah[mt][1] = *(const uint32_t*)&sA[buf][r + 8][2 * tg];
            Ah[mt][2] = *(const uint32_t*)&sA[buf][r][2 * tg + 8];
            Ah[mt][3] = *(const uint32_t*)&sA[buf][r + 8][2 * tg + 8];
        }
#pragma unroll
        for (int nt = 0; nt < 8; nt++) {
            int n = wn * 64 + nt * 8 + g;
            uint32_t bh0 = *(const uint32_t*)&sB[buf][0][n][2 * tg];
            uint32_t bh1 = *(const uint32_t*)&sB[buf][0][n][2 * tg + 8];
            uint32_t bl0 = *(const uint32_t*)&sB[buf][1][n][2 * tg];
            uint32_t bl1 = *(const uint32_t*)&sB[buf][1][n][2 * tg + 8];
#pragma unroll
            for (int mt = 0; mt < 2; mt++) {
                mma_f16(acc[mt][nt], Ah[mt], bh0, bh1);   // hi*hi
                mma_f16(acc[mt][nt], Ah[mt], bl0, bl1);   // hi*lo (weight correction)
            }
        }

        if (it + 1 < NT) {
            stageStore(buf ^ 1);
            __syncthreads();
        }
    }

    // epilogue
#pragma unroll
    for (int mt = 0; mt < 2; mt++) {
#pragma unroll
        for (int nt = 0; nt < 8; nt++) {
            int r = row0 + wm * 32 + mt * 16 + g;
            int c = col0 + wn * 64 + nt * 8 + 2 * tg;
            float c0 = acc[mt][nt][0], c1 = acc[mt][nt][1];
            float c2 = acc[mt][nt][2], c3 = acc[mt][nt][3];
            if (BIAS) {
                float b0 = bias[c], b1 = bias[c + 1];
                c0 += b0; c1 += b1; c2 += b0; c3 += b1;
            }
            if (OUTH) {
                __half* C16 = (__half*)Cout;
                if (r < M)     *(__half2*)(C16 + (size_t)r * HDIM + c)       = __floats2half2_rn(c0, c1);
                if (r + 8 < M) *(__half2*)(C16 + (size_t)(r + 8) * HDIM + c) = __floats2half2_rn(c2, c3);
            } else {
                float* C32 = (float*)Cout;
                if (r < M)     { float2 v = {c0, c1}; *(float2*)(C32 + (size_t)r * HDIM + c) = v; }
                if (r + 8 < M) { float2 v = {c2, c3}; *(float2*)(C32 + (size_t)(r + 8) * HDIM + c) = v; }
            }
        }
    }
}

// ---------------- gather conv (fp16 input): out = (Σ hw[s]·w)·dinv[d] + hw[d]·dinv[d]² + bias ----------------
__global__ void __launch_bounds__(256) gather_kernel(
    float* __restrict__ out, const __half* __restrict__ hw,
    const int* __restrict__ offs, const int* __restrict__ csr_src,
    const float* __restrict__ csr_w, const float* __restrict__ dinv,
    const float* __restrict__ bias, int M)
{
    const int node = blockIdx.x * 8 + (threadIdx.x >> 5);
    if (node >= M) return;
    const int lane = threadIdx.x & 31;
    const int col  = lane * 8;

    const int beg = offs[node];
    const int end = offs[node + 1];

    float acc[8];
#pragma unroll
    for (int i = 0; i < 8; i++) acc[i] = 0.f;

    auto accum = [&](uint4 u, float w) {
        float2 p0 = __half22float2(*(const __half2*)&u.x);
        float2 p1 = __half22float2(*(const __half2*)&u.y);
        float2 p2 = __half22float2(*(const __half2*)&u.z);
        float2 p3 = __half22float2(*(const __half2*)&u.w);
        acc[0] = fmaf(w, p0.x, acc[0]); acc[1] = fmaf(w, p0.y, acc[1]);
        acc[2] = fmaf(w, p1.x, acc[2]); acc[3] = fmaf(w, p1.y, acc[3]);
        acc[4] = fmaf(w, p2.x, acc[4]); acc[5] = fmaf(w, p2.y, acc[5]);
        acc[6] = fmaf(w, p3.x, acc[6]); acc[7] = fmaf(w, p3.y, acc[7]);
    };

    int j = beg;
    for (; j + 1 < end; j += 2) {
        int s0 = csr_src[j], s1 = csr_src[j + 1];
        float w0 = csr_w[j], w1 = csr_w[j + 1];
        uint4 u0 = *(const uint4*)(hw + (size_t)s0 * HDIM + col);
        uint4 u1 = *(const uint4*)(hw + (size_t)s1 * HDIM + col);
        accum(u0, w0);
        accum(u1, w1);
    }
    if (j < end) {
        uint4 u0 = *(const uint4*)(hw + (size_t)csr_src[j] * HDIM + col);
        accum(u0, csr_w[j]);
    }

    const float dd = dinv[node];
    const float ds = dd * dd;
    uint4 su = *(const uint4*)(hw + (size_t)node * HDIM + col);
    float2 s0 = __half22float2(*(const __half2*)&su.x);
    float2 s1 = __half22float2(*(const __half2*)&su.y);
    float2 s2 = __half22float2(*(const __half2*)&su.z);
    float2 s3 = __half22float2(*(const __half2*)&su.w);
    float sf[8] = {s0.x, s0.y, s1.x, s1.y, s2.x, s2.y, s3.x, s3.y};

    float4 bb0 = *(const float4*)(bias + col);
    float4 bb1 = *(const float4*)(bias + col + 4);
    float bf[8] = {bb0.x, bb0.y, bb0.z, bb0.w, bb1.x, bb1.y, bb1.z, bb1.w};

    float o[8];
#pragma unroll
    for (int i = 0; i < 8; i++)
        o[i] = fmaf(acc[i], dd, fmaf(sf[i], ds, bf[i]));

    float* op = out + (size_t)node * HDIM + col;
    *(float4*)op       = make_float4(o[0], o[1], o[2], o[3]);
    *(float4*)(op + 4) = make_float4(o[4], o[5], o[6], o[7]);
}

// ---------------- decoder: out[i] = relu(h[i,:]) . dec_W + dec_b ----------------
__global__ void __launch_bounds__(256) decoder_kernel(
    const float* __restrict__ h, const float* __restrict__ dw,
    const float* __restrict__ db, float* __restrict__ out, int M)
{
    int row  = blockIdx.x * (blockDim.x >> 5) + (threadIdx.x >> 5);
    int lane = threadIdx.x & 31;
    if (row >= M) return;
    const float* hr = h + (size_t)row * HDIM;
    float s = 0.f;
#pragma unroll
    for (int i = 0; i < 8; i++) {
        float v = fmaxf(hr[lane + i * 32], 0.f);
        s = fmaf(v, __ldg(&dw[lane + i * 32]), s);
    }
#pragma unroll
    for (int o = 16; o > 0; o >>= 1) s += __shfl_xor_sync(0xffffffffu, s, o);
    if (lane == 0) out[row] = s + db[0];
}

// ---------------- launch ----------------
extern "C" void kernel_launch(void* const* d_in, const int* in_sizes, int n_in,
                              void* d_out, int out_size)
{
    const float* x     = (const float*)d_in[0];
    const int*   ei    = (const int*)d_in[1];
    const float* enc_W = (const float*)d_in[2];
    const float* enc_b = (const float*)d_in[3];
    const float* W1    = (const float*)d_in[4];
    const float* b1    = (const float*)d_in[5];
    const float* W2    = (const float*)d_in[6];
    const float* b2    = (const float*)d_in[7];
    const float* W3    = (const float*)d_in[8];
    const float* b3    = (const float*)d_in[9];
    const float* decW  = (const float*)d_in[10];
    const float* decb  = (const float*)d_in[11];
    float* out = (float*)d_out;

    const int M = in_sizes[0] / 128;   // 50000
    const int E = in_sizes[1] / 2;     // 800000
    const int* src = ei;
    const int* dst = ei + E;

    float *bufA, *bufB, *dinv, *csr_w;
    __half *hwh, *WhBase, *WlBase;
    int *deg, *offs, *cur, *bsum, *csr_src;
    cudaGetSymbolAddress((void**)&bufA,    g_bufA);
    cudaGetSymbolAddress((void**)&bufB,    g_bufB);
    cudaGetSymbolAddress((void**)&hwh,     g_hwh);
    cudaGetSymbolAddress((void**)&WhBase,  g_Wh);
    cudaGetSymbolAddress((void**)&WlBase,  g_Wl);
    cudaGetSymbolAddress((void**)&deg,     g_deg);
    cudaGetSymbolAddress((void**)&dinv,    g_dinv);
    cudaGetSymbolAddress((void**)&offs,    g_offs);
    cudaGetSymbolAddress((void**)&cur,     g_cur);
    cudaGetSymbolAddress((void**)&bsum,    g_bsum);
    cudaGetSymbolAddress((void**)&csr_src, g_csr_src);
    cudaGetSymbolAddress((void**)&csr_w,   g_csr_w);

    __half* Wh[4] = {WhBase, WhBase + 65536, WhBase + 2 * 65536, WhBase + 3 * 65536};
    __half* Wl[4] = {WlBase, WlBase + 65536, WlBase + 2 * 65536, WlBase + 3 * 65536};

    const int nb = (M + 255) / 256;

    // ---- graph preprocessing ----
    deg_zero_kernel<<<nb, 256>>>(deg, M);
    deg_count_kernel<<<(E + 255) / 256, 256>>>(deg, dst, E);
    dinv_kernel<<<nb, 256>>>(dinv, deg, M);
    scan1_kernel<<<nb, 256>>>(deg, offs, bsum, M);
    scan2_kernel<<<1, 256>>>(bsum, offs, nb, M);
    scan3_kernel<<<nb, 256>>>(offs, cur, bsum, M);
    csr_fill_kernel<<<(E + 255) / 256, 256>>>(cur, csr_src, csr_w, src, dst, dinv, E);

    // ---- weight transpose + split ----
    wsplit_kernel<<<(256 * 128 + 255) / 256, 256>>>(enc_W, Wh[0], Wl[0], 128);
    wsplit_kernel<<<(256 * 256 + 255) / 256, 256>>>(W1,    Wh[1], Wl[1], 256);
    wsplit_kernel<<<(256 * 256 + 255) / 256, 256>>>(W2,    Wh[2], Wl[2], 256);
    wsplit_kernel<<<(256 * 256 + 255) / 256, 256>>>(W3,    Wh[3], Wl[3], 256);

    const dim3 gg((M + 127) / 128, 2);
    const int gat_blocks = (M + 7) / 8;

    // encoder: bufA = x @ enc_W + enc_b  (fp32 out)
    gemm_f16x2_kernel<128, true, false, false><<<gg, 256>>>(x, Wh[0], Wl[0], enc_b, bufA, M);

    // conv1: hwh = bufA @ W1 (fp16 out); bufB = gather(hwh) + b1
    gemm_f16x2_kernel<256, false, false, true><<<gg, 256>>>(bufA, Wh[1], Wl[1], nullptr, hwh, M);
    gather_kernel<<<gat_blocks, 256>>>(bufB, hwh, offs, csr_src, csr_w, dinv, b1, M);

    // conv2 (relu fused into GEMM A-load)
    gemm_f16x2_kernel<256, false, true, true><<<gg, 256>>>(bufB, Wh[2], Wl[2], nullptr, hwh, M);
    gather_kernel<<<gat_blocks, 256>>>(bufA, hwh, offs, csr_src, csr_w, dinv, b2, M);

    // conv3
    gemm_f16x2_kernel<256, false, true, true><<<gg, 256>>>(bufA, Wh[3], Wl[3], nullptr, hwh, M);
    gather_kernel<<<gat_blocks, 256>>>(bufB, hwh, offs, csr_src, csr_w, dinv, b3, M);

    // decoder (relu fused)
    decoder_kernel<<<(M + 7) / 8, 256>>>(bufB, decW, decb, out, M);
}

// round 8
// speedup vs baseline: 3.3436x; 1.3372x over previous
#include <cuda_runtime.h>
#include <cuda_fp16.h>
#include <cstdint>

#define NNODES 50000
#define EDGES  800000
#define HDIM   256

// ---------------- scratch (no allocations allowed) ----------------
__device__ float  g_bufA[NNODES * HDIM];
__device__ float  g_bufB[NNODES * HDIM];
__device__ __half g_hwh[NNODES * HDIM];
__device__ __half g_Wh[4][65536];
__device__ int    g_deg[NNODES];
__device__ float  g_dinv[NNODES];
__device__ int    g_offs[NNODES + 1];
__device__ int    g_cur[NNODES];
__device__ int    g_bsum[256];
__device__ int    g_csr_src[EDGES];
__device__ float  g_csr_w[EDGES];

// ---------------- degree / dinv ----------------
__global__ void deg_zero_kernel(int* __restrict__ deg, int n) {
    int i = blockIdx.x * blockDim.x + threadIdx.x;
    if (i < n) deg[i] = 0;
}

__global__ void deg_count_kernel(int* __restrict__ deg, const int* __restrict__ dst, int E) {
    int e = blockIdx.x * blockDim.x + threadIdx.x;
    if (e < E) atomicAdd(&deg[dst[e]], 1);
}

__global__ void dinv_kernel(float* __restrict__ dinv, const int* __restrict__ deg, int n) {
    int i = blockIdx.x * blockDim.x + threadIdx.x;
    if (i < n) dinv[i] = rsqrtf((float)(deg[i] + 1));  // +1 self-loop
}

// ---------------- 3-pass scan (multi-block) ----------------
__global__ void scan1_kernel(const int* __restrict__ deg, int* __restrict__ offs,
                             int* __restrict__ bsum, int n)
{
    __shared__ int sh[256];
    const int t = threadIdx.x;
    const int i = blockIdx.x * 256 + t;
    int v = (i < n) ? deg[i] : 0;
    sh[t] = v;
    __syncthreads();
#pragma unroll
    for (int off = 1; off < 256; off <<= 1) {
        int x = (t >= off) ? sh[t - off] : 0;
        __syncthreads();
        sh[t] += x;
        __syncthreads();
    }
    if (i < n) offs[i] = sh[t] - v;
    if (t == 255) bsum[blockIdx.x] = sh[255];
}

__global__ void scan2_kernel(int* __restrict__ bsum, int* __restrict__ offs, int nb, int n)
{
    __shared__ int sh[256];
    const int t = threadIdx.x;
    int v = (t < nb) ? bsum[t] : 0;
    sh[t] = v;
    __syncthreads();
#pragma unroll
    for (int off = 1; off < 256; off <<= 1) {
        int x = (t >= off) ? sh[t - off] : 0;
        __syncthreads();
        sh[t] += x;
        __syncthreads();
    }
    if (t < nb) bsum[t] = sh[t] - v;
    if (t == 255) offs[n] = sh[255];
}

__global__ void scan3_kernel(int* __restrict__ offs, int* __restrict__ cur,
                             const int* __restrict__ bsum, int n)
{
    int i = blockIdx.x * blockDim.x + threadIdx.x;
    if (i < n) {
        int o = offs[i] + bsum[i >> 8];
        offs[i] = o;
        cur[i]  = o;
    }
}

// ---------------- CSR fill (w fused) ----------------
__global__ void csr_fill_kernel(int* __restrict__ cur, int* __restrict__ csr_src,
                                float* __restrict__ csr_w,
                                const int* __restrict__ src, const int* __restrict__ dst,
                                const float* __restrict__ dinv, int E)
{
    int e = blockIdx.x * blockDim.x + threadIdx.x;
    if (e >= E) return;
    int s = src[e];
    int p = atomicAdd(&cur[dst[e]], 1);
    csr_src[p] = s;
    csr_w[p]   = dinv[s];
}

// ---------------- weight transpose to fp16 (once per layer) ----------------
// W[k][256] fp32 -> Wt[n][K] fp16 (n-major, k contiguous)
__global__ void wsplit_kernel(const float* __restrict__ W, __half* __restrict__ Wh, int K)
{
    int idx = blockIdx.x * 256 + threadIdx.x;   // idx = n*K + k
    if (idx >= 256 * K) return;
    int n = idx / K, k = idx - n * K;
    Wh[idx] = __float2half_rn(W[k * 256 + n]);
}

// ---------------- fp16 tensor-core GEMM with ldmatrix ----------------
// C[M,256] = A[M,K] @ W[K,256] (+bias), fp32 accumulate.
// Tile 128x128, BK=16, 256 threads = 8 warps (4m x 2n), warp tile 32x64.

__device__ __forceinline__ void mma_f16(float* c, const uint32_t* a, uint32_t b0, uint32_t b1) {
    asm volatile("mma.sync.aligned.m16n8k16.row.col.f32.f16.f16.f32 "
        "{%0,%1,%2,%3}, {%4,%5,%6,%7}, {%8,%9}, {%0,%1,%2,%3};"
        : "+f"(c[0]), "+f"(c[1]), "+f"(c[2]), "+f"(c[3])
        : "r"(a[0]), "r"(a[1]), "r"(a[2]), "r"(a[3]), "r"(b0), "r"(b1));
}

__device__ __forceinline__ void ldm_x4(uint32_t* r, uint32_t saddr) {
    asm volatile("ldmatrix.sync.aligned.m8n8.x4.shared.b16 {%0,%1,%2,%3}, [%4];"
        : "=r"(r[0]), "=r"(r[1]), "=r"(r[2]), "=r"(r[3]) : "r"(saddr));
}

template <int K, bool BIAS, bool RELU_A, bool OUTH>
__global__ void __launch_bounds__(256) gemm_f16_kernel(
    const float* __restrict__ A, const __half* __restrict__ Wh,
    const float* __restrict__ bias, void* __restrict__ Cout, int M)
{
    // [buf][row-or-n][k(16)+pad(8)]; row stride 48B -> 8 rows hit 8 distinct banks
    __shared__ __half sA[2][128][24];
    __shared__ __half sB[2][128][24];

    const int tid  = threadIdx.x;
    const int lane = tid & 31;
    const int wid  = tid >> 5;
    const int wm   = wid >> 1;           // 0..3 (m 32-group)
    const int wn   = wid & 1;            // 0..1 (n 64-group)
    const int g    = lane >> 2;          // 0..7
    const int tg   = lane & 3;           // 0..3
    const int row0 = blockIdx.x * 128;
    const int col0 = blockIdx.y * 128;

    // loaders
    const int ar  = tid >> 1;
    const int ak8 = (tid & 1) * 8;
    const int bn  = tid & 127;
    const int bh8 = (tid >> 7) * 8;

    const int arow = row0 + ar;
    const bool a_ok = (arow < M);
    const float*  Aptr = A + (size_t)arow * K + ak8;
    const __half* Bph  = Wh + (size_t)(col0 + bn) * K + bh8;

    // ldmatrix per-lane byte offsets within a buffer plane (row*48 + col*2)
    const int l8 = lane & 7;
    // A: lanes 0-7 rows+0/k0, 8-15 rows+8/k0, 16-23 rows+0/k8, 24-31 rows+8/k8
    const int a_r  = ((lane >> 3) & 1) * 8 + l8;
    const int a_k  = (lane >> 4) * 8;
    // B: lanes 0-7 n+0/k0, 8-15 n+0/k8, 16-23 n+8/k0, 24-31 n+8/k8
    const int b_n  = ((lane >> 4) & 1) * 8 + l8;
    const int b_k  = ((lane >> 3) & 1) * 8;

    const uint32_t sA_base = (uint32_t)__cvta_generic_to_shared(&sA[0][0][0]);
    const uint32_t sB_base = (uint32_t)__cvta_generic_to_shared(&sB[0][0][0]);
    const uint32_t aoff0 = (uint32_t)((wm * 32 + a_r) * 48 + a_k * 2);
    const uint32_t boff0 = (uint32_t)((wn * 64 + b_n) * 48 + b_k * 2);
    const uint32_t bufstride = 128 * 48;

    float acc[2][8][4];
#pragma unroll
    for (int mt = 0; mt < 2; mt++)
#pragma unroll
        for (int nt = 0; nt < 8; nt++)
#pragma unroll
            for (int r = 0; r < 4; r++) acc[mt][nt][r] = 0.f;

    const int NT = K / 16;

    float4 av0 = make_float4(0.f, 0.f, 0.f, 0.f), av1 = av0;
    uint4 bvh;

    if (a_ok) { av0 = *(const float4*)Aptr; av1 = *(const float4*)(Aptr + 4); }
    bvh = *(const uint4*)Bph;

    auto stageStore = [&](int b) {
        float f[8] = {av0.x, av0.y, av0.z, av0.w, av1.x, av1.y, av1.z, av1.w};
        __half hb[8];
#pragma unroll
        for (int j = 0; j < 8; j++) {
            float x = f[j];
            if (RELU_A) x = fmaxf(x, 0.f);
            hb[j] = __float2half_rn(x);
        }
        *(uint4*)&sA[b][ar][ak8] = *(const uint4*)hb;
        *(uint4*)&sB[b][bn][bh8] = bvh;
    };

    stageStore(0);
    __syncthreads();

    for (int it = 0; it < NT; it++) {
        const int buf = it & 1;
        if (it + 1 < NT) {
            const int off = (it + 1) * 16;
            if (a_ok) { av0 = *(const float4*)(Aptr + off); av1 = *(const float4*)(Aptr + off + 4); }
            bvh = *(const uint4*)(Bph + off);
        }

        // A fragments: 2 ldmatrix.x4 (one per 16-row mt tile)
        uint32_t Af[2][4];
#pragma unroll
        for (int mt = 0; mt < 2; mt++)
            ldm_x4(Af[mt], sA_base + buf * bufstride + aoff0 + mt * 16 * 48);

        // B fragments: 4 ldmatrix.x4 (each covers two nt tiles of 8 n)
        uint32_t Bf[8][2];
#pragma unroll
        for (int q = 0; q < 4; q++) {
            uint32_t r[4];
            ldm_x4(r, sB_base + buf * bufstride + boff0 + q * 16 * 48);
            Bf[2 * q][0]     = r[0]; Bf[2 * q][1]     = r[1];
            Bf[2 * q + 1][0] = r[2]; Bf[2 * q + 1][1] = r[3];
        }

#pragma unroll
        for (int nt = 0; nt < 8; nt++)
#pragma unroll
            for (int mt = 0; mt < 2; mt++)
                mma_f16(acc[mt][nt], Af[mt], Bf[nt][0], Bf[nt][1]);

        if (it + 1 < NT) {
            stageStore(buf ^ 1);
            __syncthreads();
        }
    }

    // epilogue
#pragma unroll
    for (int mt = 0; mt < 2; mt++) {
#pragma unroll
        for (int nt = 0; nt < 8; nt++) {
            int r = row0 + wm * 32 + mt * 16 + g;
            int c = col0 + wn * 64 + nt * 8 + 2 * tg;
            float c0 = acc[mt][nt][0], c1 = acc[mt][nt][1];
            float c2 = acc[mt][nt][2], c3 = acc[mt][nt][3];
            if (BIAS) {
                float b0 = bias[c], b1 = bias[c + 1];
                c0 += b0; c1 += b1; c2 += b0; c3 += b1;
            }
            if (OUTH) {
                __half* C16 = (__half*)Cout;
                if (r < M)     *(__half2*)(C16 + (size_t)r * HDIM + c)       = __floats2half2_rn(c0, c1);
                if (r + 8 < M) *(__half2*)(C16 + (size_t)(r + 8) * HDIM + c) = __floats2half2_rn(c2, c3);
            } else {
                float* C32 = (float*)Cout;
                if (r < M)     { float2 v = {c0, c1}; *(float2*)(C32 + (size_t)r * HDIM + c) = v; }
                if (r + 8 < M) { float2 v = {c2, c3}; *(float2*)(C32 + (size_t)(r + 8) * HDIM + c) = v; }
            }
        }
    }
}

// ---------------- gather conv (fp16 input): out = (Σ hw[s]·w)·dinv[d] + hw[d]·dinv[d]² + bias ----------------
__global__ void __launch_bounds__(256) gather_kernel(
    float* __restrict__ out, const __half* __restrict__ hw,
    const int* __restrict__ offs, const int* __restrict__ csr_src,
    const float* __restrict__ csr_w, const float* __restrict__ dinv,
    const float* __restrict__ bias, int M)
{
    const int node = blockIdx.x * 8 + (threadIdx.x >> 5);
    if (node >= M) return;
    const int lane = threadIdx.x & 31;
    const int col  = lane * 8;

    const int beg = offs[node];
    const int end = offs[node + 1];

    float acc[8];
#pragma unroll
    for (int i = 0; i < 8; i++) acc[i] = 0.f;

    auto accum = [&](uint4 u, float w) {
        float2 p0 = __half22float2(*(const __half2*)&u.x);
        float2 p1 = __half22float2(*(const __half2*)&u.y);
        float2 p2 = __half22float2(*(const __half2*)&u.z);
        float2 p3 = __half22float2(*(const __half2*)&u.w);
        acc[0] = fmaf(w, p0.x, acc[0]); acc[1] = fmaf(w, p0.y, acc[1]);
        acc[2] = fmaf(w, p1.x, acc[2]); acc[3] = fmaf(w, p1.y, acc[3]);
        acc[4] = fmaf(w, p2.x, acc[4]); acc[5] = fmaf(w, p2.y, acc[5]);
        acc[6] = fmaf(w, p3.x, acc[6]); acc[7] = fmaf(w, p3.y, acc[7]);
    };

    int j = beg;
    for (; j + 1 < end; j += 2) {
        int s0 = csr_src[j], s1 = csr_src[j + 1];
        float w0 = csr_w[j], w1 = csr_w[j + 1];
        uint4 u0 = *(const uint4*)(hw + (size_t)s0 * HDIM + col);
        uint4 u1 = *(const uint4*)(hw + (size_t)s1 * HDIM + col);
        accum(u0, w0);
        accum(u1, w1);
    }
    if (j < end) {
        uint4 u0 = *(const uint4*)(hw + (size_t)csr_src[j] * HDIM + col);
        accum(u0, csr_w[j]);
    }

    const float dd = dinv[node];
    const float ds = dd * dd;
    uint4 su = *(const uint4*)(hw + (size_t)node * HDIM + col);
    float2 s0 = __half22float2(*(const __half2*)&su.x);
    float2 s1 = __half22float2(*(const __half2*)&su.y);
    float2 s2 = __half22float2(*(const __half2*)&su.z);
    float2 s3 = __half22float2(*(const __half2*)&su.w);
    float sf[8] = {s0.x, s0.y, s1.x, s1.y, s2.x, s2.y, s3.x, s3.y};

    float4 bb0 = *(const float4*)(bias + col);
    float4 bb1 = *(const float4*)(bias + col + 4);
    float bf[8] = {bb0.x, bb0.y, bb0.z, bb0.w, bb1.x, bb1.y, bb1.z, bb1.w};

    float o[8];
#pragma unroll
    for (int i = 0; i < 8; i++)
        o[i] = fmaf(acc[i], dd, fmaf(sf[i], ds, bf[i]));

    float* op = out + (size_t)node * HDIM + col;
    *(float4*)op       = make_float4(o[0], o[1], o[2], o[3]);
    *(float4*)(op + 4) = make_float4(o[4], o[5], o[6], o[7]);
}

// ---------------- decoder: out[i] = relu(h[i,:]) . dec_W + dec_b ----------------
__global__ void __launch_bounds__(256) decoder_kernel(
    const float* __restrict__ h, const float* __restrict__ dw,
    const float* __restrict__ db, float* __restrict__ out, int M)
{
    int row  = blockIdx.x * (blockDim.x >> 5) + (threadIdx.x >> 5);
    int lane = threadIdx.x & 31;
    if (row >= M) return;
    const float* hr = h + (size_t)row * HDIM;
    float s = 0.f;
#pragma unroll
    for (int i = 0; i < 8; i++) {
        float v = fmaxf(hr[lane + i * 32], 0.f);
        s = fmaf(v, __ldg(&dw[lane + i * 32]), s);
    }
#pragma unroll
    for (int o = 16; o > 0; o >>= 1) s += __shfl_xor_sync(0xffffffffu, s, o);
    if (lane == 0) out[row] = s + db[0];
}

// ---------------- launch ----------------
extern "C" void kernel_launch(void* const* d_in, const int* in_sizes, int n_in,
                              void* d_out, int out_size)
{
    const float* x     = (const float*)d_in[0];
    const int*   ei    = (const int*)d_in[1];
    const float* enc_W = (const float*)d_in[2];
    const float* enc_b = (const float*)d_in[3];
    const float* W1    = (const float*)d_in[4];
    const float* b1    = (const float*)d_in[5];
    const float* W2    = (const float*)d_in[6];
    const float* b2    = (const float*)d_in[7];
    const float* W3    = (const float*)d_in[8];
    const float* b3    = (const float*)d_in[9];
    const float* decW  = (const float*)d_in[10];
    const float* decb  = (const float*)d_in[11];
    float* out = (float*)d_out;

    const int M = in_sizes[0] / 128;   // 50000
    const int E = in_sizes[1] / 2;     // 800000
    const int* src = ei;
    const int* dst = ei + E;

    float *bufA, *bufB, *dinv, *csr_w;
    __half *hwh, *WhBase;
    int *deg, *offs, *cur, *bsum, *csr_src;
    cudaGetSymbolAddress((void**)&bufA,    g_bufA);
    cudaGetSymbolAddress((void**)&bufB,    g_bufB);
    cudaGetSymbolAddress((void**)&hwh,     g_hwh);
    cudaGetSymbolAddress((void**)&WhBase,  g_Wh);
    cudaGetSymbolAddress((void**)&deg,     g_deg);
    cudaGetSymbolAddress((void**)&dinv,    g_dinv);
    cudaGetSymbolAddress((void**)&offs,    g_offs);
    cudaGetSymbolAddress((void**)&cur,     g_cur);
    cudaGetSymbolAddress((void**)&bsum,    g_bsum);
    cudaGetSymbolAddress((void**)&csr_src, g_csr_src);
    cudaGetSymbolAddress((void**)&csr_w,   g_csr_w);

    __half* Wh[4] = {WhBase, WhBase + 65536, WhBase + 2 * 65536, WhBase + 3 * 65536};

    const int nb = (M + 255) / 256;

    // ---- graph preprocessing ----
    deg_zero_kernel<<<nb, 256>>>(deg, M);
    deg_count_kernel<<<(E + 255) / 256, 256>>>(deg, dst, E);
    dinv_kernel<<<nb, 256>>>(dinv, deg, M);
    scan1_kernel<<<nb, 256>>>(deg, offs, bsum, M);
    scan2_kernel<<<1, 256>>>(bsum, offs, nb, M);
    scan3_kernel<<<nb, 256>>>(offs, cur, bsum, M);
    csr_fill_kernel<<<(E + 255) / 256, 256>>>(cur, csr_src, csr_w, src, dst, dinv, E);

    // ---- weight transpose to fp16 ----
    wsplit_kernel<<<(256 * 128 + 255) / 256, 256>>>(enc_W, Wh[0], 128);
    wsplit_kernel<<<(256 * 256 + 255) / 256, 256>>>(W1,    Wh[1], 256);
    wsplit_kernel<<<(256 * 256 + 255) / 256, 256>>>(W2,    Wh[2], 256);
    wsplit_kernel<<<(256 * 256 + 255) / 256, 256>>>(W3,    Wh[3], 256);

    const dim3 gg((M + 127) / 128, 2);
    const int gat_blocks = (M + 7) / 8;

    // encoder: bufA = x @ enc_W + enc_b  (fp32 out)
    gemm_f16_kernel<128, true, false, false><<<gg, 256>>>(x, Wh[0], enc_b, bufA, M);

    // conv1: hwh = bufA @ W1 (fp16 out); bufB = gather(hwh) + b1
    gemm_f16_kernel<256, false, false, true><<<gg, 256>>>(bufA, Wh[1], nullptr, hwh, M);
    gather_kernel<<<gat_blocks, 256>>>(bufB, hwh, offs, csr_src, csr_w, dinv, b1, M);

    // conv2 (relu fused into GEMM A-load)
    gemm_f16_kernel<256, false, true, true><<<gg, 256>>>(bufB, Wh[2], nullptr, hwh, M);
    gather_kernel<<<gat_blocks, 256>>>(bufA, hwh, offs, csr_src, csr_w, dinv, b2, M);

    // conv3
    gemm_f16_kernel<256, false, true, true><<<gg, 256>>>(bufA, Wh[3], nullptr, hwh, M);
    gather_kernel<<<gat_blocks, 256>>>(bufB, hwh, offs, csr_src, csr_w, dinv, b3, M);

    // decoder (relu fused)
    decoder_kernel<<<(M + 7) / 8, 256>>>(bufB, decW, decb, out, M);
}

// round 9
// speedup vs baseline: 3.7818x; 1.1310x over previous
#include <cuda_runtime.h>
#include <cuda_fp16.h>
#include <cstdint>

#define NNODES 50000
#define EDGES  800000
#define HDIM   256

// ---------------- scratch (no allocations allowed) ----------------
__device__ __half g_actA[NNODES * HDIM];
__device__ __half g_actB[NNODES * HDIM];
__device__ __half g_hwh[NNODES * HDIM];    // GEMM out for convs; also holds x16 for encoder
__device__ __half g_Wh[4][65536];
__device__ int    g_deg[NNODES];
__device__ float  g_dinv[NNODES];
__device__ int    g_offs[NNODES + 1];
__device__ int    g_cur[NNODES];
__device__ int    g_bsum[256];
__device__ int    g_csr_src[EDGES];
__device__ float  g_csr_w[EDGES];

// ---------------- degree / dinv ----------------
__global__ void deg_zero_kernel(int* __restrict__ deg, int n) {
    int i = blockIdx.x * blockDim.x + threadIdx.x;
    if (i < n) deg[i] = 0;
}

__global__ void deg_count_kernel(int* __restrict__ deg, const int* __restrict__ dst, int E) {
    int e = blockIdx.x * blockDim.x + threadIdx.x;
    if (e < E) atomicAdd(&deg[dst[e]], 1);
}

__global__ void dinv_kernel(float* __restrict__ dinv, const int* __restrict__ deg, int n) {
    int i = blockIdx.x * blockDim.x + threadIdx.x;
    if (i < n) dinv[i] = rsqrtf((float)(deg[i] + 1));  // +1 self-loop
}

// ---------------- 3-pass scan (multi-block) ----------------
__global__ void scan1_kernel(const int* __restrict__ deg, int* __restrict__ offs,
                             int* __restrict__ bsum, int n)
{
    __shared__ int sh[256];
    const int t = threadIdx.x;
    const int i = blockIdx.x * 256 + t;
    int v = (i < n) ? deg[i] : 0;
    sh[t] = v;
    __syncthreads();
#pragma unroll
    for (int off = 1; off < 256; off <<= 1) {
        int x = (t >= off) ? sh[t - off] : 0;
        __syncthreads();
        sh[t] += x;
        __syncthreads();
    }
    if (i < n) offs[i] = sh[t] - v;
    if (t == 255) bsum[blockIdx.x] = sh[255];
}

__global__ void scan2_kernel(int* __restrict__ bsum, int* __restrict__ offs, int nb, int n)
{
    __shared__ int sh[256];
    const int t = threadIdx.x;
    int v = (t < nb) ? bsum[t] : 0;
    sh[t] = v;
    __syncthreads();
#pragma unroll
    for (int off = 1; off < 256; off <<= 1) {
        int x = (t >= off) ? sh[t - off] : 0;
        __syncthreads();
        sh[t] += x;
        __syncthreads();
    }
    if (t < nb) bsum[t] = sh[t] - v;
    if (t == 255) offs[n] = sh[255];
}

__global__ void scan3_kernel(int* __restrict__ offs, int* __restrict__ cur,
                             const int* __restrict__ bsum, int n)
{
    int i = blockIdx.x * blockDim.x + threadIdx.x;
    if (i < n) {
        int o = offs[i] + bsum[i >> 8];
        offs[i] = o;
        cur[i]  = o;
    }
}

// ---------------- CSR fill (w fused) ----------------
__global__ void csr_fill_kernel(int* __restrict__ cur, int* __restrict__ csr_src,
                                float* __restrict__ csr_w,
                                const int* __restrict__ src, const int* __restrict__ dst,
                                const float* __restrict__ dinv, int E)
{
    int e = blockIdx.x * blockDim.x + threadIdx.x;
    if (e >= E) return;
    int s = src[e];
    int p = atomicAdd(&cur[dst[e]], 1);
    csr_src[p] = s;
    csr_w[p]   = dinv[s];
}

// ---------------- weight transpose to fp16 (once per layer) ----------------
__global__ void wsplit_kernel(const float* __restrict__ W, __half* __restrict__ Wh, int K)
{
    int idx = blockIdx.x * 256 + threadIdx.x;   // idx = n*K + k
    if (idx >= 256 * K) return;
    int n = idx / K, k = idx - n * K;
    Wh[idx] = __float2half_rn(W[k * 256 + n]);
}

// ---------------- x -> fp16 convert ----------------
__global__ void x16_kernel(const float* __restrict__ x, __half* __restrict__ xh, int total4)
{
    int i = blockIdx.x * 256 + threadIdx.x;   // over float4s
    if (i >= total4) return;
    float4 v = *(const float4*)(x + 4 * (size_t)i);
    __half2 a = __floats2half2_rn(v.x, v.y);
    __half2 b = __floats2half2_rn(v.z, v.w);
    *(uint2*)(xh + 4 * (size_t)i) = make_uint2(*(uint32_t*)&a, *(uint32_t*)&b);
}

// ---------------- fp16 tensor-core GEMM: cp.async + ldmatrix ----------------
// C[M,256] = A[M,K] @ W[K,256] (+bias), fp32 accumulate, fp16 out.
// Tile 128x128, BK=16, 256 threads = 8 warps (4m x 2n), warp tile 32x64.
// ReLU applied to A fragments post-ldmatrix (hmax2).

__device__ __forceinline__ void mma_f16(float* c, const uint32_t* a, uint32_t b0, uint32_t b1) {
    asm volatile("mma.sync.aligned.m16n8k16.row.col.f32.f16.f16.f32 "
        "{%0,%1,%2,%3}, {%4,%5,%6,%7}, {%8,%9}, {%0,%1,%2,%3};"
        : "+f"(c[0]), "+f"(c[1]), "+f"(c[2]), "+f"(c[3])
        : "r"(a[0]), "r"(a[1]), "r"(a[2]), "r"(a[3]), "r"(b0), "r"(b1));
}

__device__ __forceinline__ void ldm_x4(uint32_t* r, uint32_t saddr) {
    asm volatile("ldmatrix.sync.aligned.m8n8.x4.shared.b16 {%0,%1,%2,%3}, [%4];"
        : "=r"(r[0]), "=r"(r[1]), "=r"(r[2]), "=r"(r[3]) : "r"(saddr));
}

__device__ __forceinline__ void cpa16(uint32_t saddr, const void* gaddr, int szr) {
    asm volatile("cp.async.cg.shared.global [%0], [%1], 16, %2;"
        :: "r"(saddr), "l"(gaddr), "r"(szr));
}

template <int K, bool BIAS, bool RELU_A>
__global__ void __launch_bounds__(256) gemm_f16_kernel(
    const __half* __restrict__ A, const __half* __restrict__ Wh,
    const float* __restrict__ bias, __half* __restrict__ Cout, int M)
{
    // [buf][row-or-n][k(16)+pad(8)]; row stride 48B -> conflict-free ldmatrix
    __shared__ __half sA[2][128][24];
    __shared__ __half sB[2][128][24];

    const int tid  = threadIdx.x;
    const int lane = tid & 31;
    const int wid  = tid >> 5;
    const int wm   = wid >> 1;
    const int wn   = wid & 1;
    const int g    = lane >> 2;
    const int tg   = lane & 3;
    const int row0 = blockIdx.x * 128;
    const int col0 = blockIdx.y * 128;

    // loaders: one 16B cp.async per thread per matrix per stage
    const int ar  = tid >> 1;
    const int ak8 = (tid & 1) * 8;
    const int bn  = tid & 127;
    const int bh8 = (tid >> 7) * 8;

    const int arow = row0 + ar;
    const int asz  = (arow < M) ? 16 : 0;       // zero-fill OOB rows
    const __half* Aptr = A + (size_t)arow * K + ak8;
    const __half* Bph  = Wh + (size_t)(col0 + bn) * K + bh8;

    const uint32_t sA_base = (uint32_t)__cvta_generic_to_shared(&sA[0][0][0]);
    const uint32_t sB_base = (uint32_t)__cvta_generic_to_shared(&sB[0][0][0]);
    const uint32_t bufstride = 128 * 48;
    const uint32_t ast = sA_base + ar * 48 + ak8 * 2;
    const uint32_t bst = sB_base + bn * 48 + bh8 * 2;

    // ldmatrix per-lane offsets
    const int l8 = lane & 7;
    const int a_r = ((lane >> 3) & 1) * 8 + l8;
    const int a_k = (lane >> 4) * 8;
    const int b_n = ((lane >> 4) & 1) * 8 + l8;
    const int b_k = ((lane >> 3) & 1) * 8;
    const uint32_t aoff0 = (uint32_t)((wm * 32 + a_r) * 48 + a_k * 2);
    const uint32_t boff0 = (uint32_t)((wn * 64 + b_n) * 48 + b_k * 2);

    float acc[2][8][4];
#pragma unroll
    for (int mt = 0; mt < 2; mt++)
#pragma unroll
        for (int nt = 0; nt < 8; nt++)
#pragma unroll
            for (int r = 0; r < 4; r++) acc[mt][nt][r] = 0.f;

    const int NT = K / 16;

    // stage 0
    cpa16(ast, Aptr, asz);
    cpa16(bst, Bph, 16);
    asm volatile("cp.async.commit_group;");

    const __half2 zero2 = __float2half2_rn(0.f);

    for (int it = 0; it < NT; it++) {
        const int buf = it & 1;
        asm volatile("cp.async.wait_group 0;");
        __syncthreads();

        // issue next stage (overlaps with math below)
        if (it + 1 < NT) {
            const int off = (it + 1) * 16;
            const uint32_t nb = (buf ^ 1) * bufstride;
            cpa16(ast + nb, Aptr + off, asz);
            cpa16(bst + nb, Bph + off, 16);
            asm volatile("cp.async.commit_group;");
        }

        // A fragments
        uint32_t Af[2][4];
#pragma unroll
        for (int mt = 0; mt < 2; mt++) {
            ldm_x4(Af[mt], sA_base + buf * bufstride + aoff0 + mt * 16 * 48);
            if (RELU_A) {
#pragma unroll
                for (int j = 0; j < 4; j++) {
                    __half2 h = *(__half2*)&Af[mt][j];
                    h = __hmax2(h, zero2);
                    Af[mt][j] = *(uint32_t*)&h;
                }
            }
        }

        // B fragments
        uint32_t Bf[8][2];
#pragma unroll
        for (int q = 0; q < 4; q++) {
            uint32_t r[4];
            ldm_x4(r, sB_base + buf * bufstride + boff0 + q * 16 * 48);
            Bf[2 * q][0]     = r[0]; Bf[2 * q][1]     = r[1];
            Bf[2 * q + 1][0] = r[2]; Bf[2 * q + 1][1] = r[3];
        }

#pragma unroll
        for (int nt = 0; nt < 8; nt++)
#pragma unroll
            for (int mt = 0; mt < 2; mt++)
                mma_f16(acc[mt][nt], Af[mt], Bf[nt][0], Bf[nt][1]);
    }

    // epilogue (fp16 out)
#pragma unroll
    for (int mt = 0; mt < 2; mt++) {
#pragma unroll
        for (int nt = 0; nt < 8; nt++) {
            int r = row0 + wm * 32 + mt * 16 + g;
            int c = col0 + wn * 64 + nt * 8 + 2 * tg;
            float c0 = acc[mt][nt][0], c1 = acc[mt][nt][1];
            float c2 = acc[mt][nt][2], c3 = acc[mt][nt][3];
            if (BIAS) {
                float b0 = bias[c], b1 = bias[c + 1];
                c0 += b0; c1 += b1; c2 += b0; c3 += b1;
            }
            if (r < M)     *(__half2*)(Cout + (size_t)r * HDIM + c)       = __floats2half2_rn(c0, c1);
            if (r + 8 < M) *(__half2*)(Cout + (size_t)(r + 8) * HDIM + c) = __floats2half2_rn(c2, c3);
        }
    }
}

// ---------------- gather conv (fp16 in/out): out = (Σ hw[s]·w)·dinv[d] + hw[d]·dinv[d]² + bias ----------------
__global__ void __launch_bounds__(256) gather_kernel(
    __half* __restrict__ out, const __half* __restrict__ hw,
    const int* __restrict__ offs, const int* __restrict__ csr_src,
    const float* __restrict__ csr_w, const float* __restrict__ dinv,
    const float* __restrict__ bias, int M)
{
    const int node = blockIdx.x * 8 + (threadIdx.x >> 5);
    if (node >= M) return;
    const int lane = threadIdx.x & 31;
    const int col  = lane * 8;

    const int beg = offs[node];
    const int end = offs[node + 1];

    float acc[8];
#pragma unroll
    for (int i = 0; i < 8; i++) acc[i] = 0.f;

    auto accum = [&](uint4 u, float w) {
        float2 p0 = __half22float2(*(const __half2*)&u.x);
        float2 p1 = __half22float2(*(const __half2*)&u.y);
        float2 p2 = __half22float2(*(const __half2*)&u.z);
        float2 p3 = __half22float2(*(const __half2*)&u.w);
        acc[0] = fmaf(w, p0.x, acc[0]); acc[1] = fmaf(w, p0.y, acc[1]);
        acc[2] = fmaf(w, p1.x, acc[2]); acc[3] = fmaf(w, p1.y, acc[3]);
        acc[4] = fmaf(w, p2.x, acc[4]); acc[5] = fmaf(w, p2.y, acc[5]);
        acc[6] = fmaf(w, p3.x, acc[6]); acc[7] = fmaf(w, p3.y, acc[7]);
    };

    int j = beg;
    for (; j + 1 < end; j += 2) {
        int s0 = csr_src[j], s1 = csr_src[j + 1];
        float w0 = csr_w[j], w1 = csr_w[j + 1];
        uint4 u0 = *(const uint4*)(hw + (size_t)s0 * HDIM + col);
        uint4 u1 = *(const uint4*)(hw + (size_t)s1 * HDIM + col);
        accum(u0, w0);
        accum(u1, w1);
    }
    if (j < end) {
        uint4 u0 = *(const uint4*)(hw + (size_t)csr_src[j] * HDIM + col);
        accum(u0, csr_w[j]);
    }

    const float dd = dinv[node];
    const float ds = dd * dd;
    uint4 su = *(const uint4*)(hw + (size_t)node * HDIM + col);
    float2 s0 = __half22float2(*(const __half2*)&su.x);
    float2 s1 = __half22float2(*(const __half2*)&su.y);
    float2 s2 = __half22float2(*(const __half2*)&su.z);
    float2 s3 = __half22float2(*(const __half2*)&su.w);
    float sf[8] = {s0.x, s0.y, s1.x, s1.y, s2.x, s2.y, s3.x, s3.y};

    float4 bb0 = *(const float4*)(bias + col);
    float4 bb1 = *(const float4*)(bias + col + 4);
    float bf[8] = {bb0.x, bb0.y, bb0.z, bb0.w, bb1.x, bb1.y, bb1.z, bb1.w};

    __half2 o[4];
#pragma unroll
    for (int i = 0; i < 4; i++) {
        float e0 = fmaf(acc[2*i],   dd, fmaf(sf[2*i],   ds, bf[2*i]));
        float e1 = fmaf(acc[2*i+1], dd, fmaf(sf[2*i+1], ds, bf[2*i+1]));
        o[i] = __floats2half2_rn(e0, e1);
    }
    *(uint4*)(out + (size_t)node * HDIM + col) = *(uint4*)o;
}

// ---------------- decoder: out[i] = relu(h[i,:]) . dec_W + dec_b ----------------
__global__ void __launch_bounds__(256) decoder_kernel(
    const __half* __restrict__ h, const float* __restrict__ dw,
    const float* __restrict__ db, float* __restrict__ out, int M)
{
    int row  = blockIdx.x * (blockDim.x >> 5) + (threadIdx.x >> 5);
    int lane = threadIdx.x & 31;
    if (row >= M) return;
    const __half* hr = h + (size_t)row * HDIM;
    float s = 0.f;
#pragma unroll
    for (int i = 0; i < 8; i++) {
        float v = fmaxf(__half2float(hr[lane + i * 32]), 0.f);
        s = fmaf(v, __ldg(&dw[lane + i * 32]), s);
    }
#pragma unroll
    for (int o = 16; o > 0; o >>= 1) s += __shfl_xor_sync(0xffffffffu, s, o);
    if (lane == 0) out[row] = s + db[0];
}

// ---------------- launch ----------------
extern "C" void kernel_launch(void* const* d_in, const int* in_sizes, int n_in,
                              void* d_out, int out_size)
{
    const float* x     = (const float*)d_in[0];
    const int*   ei    = (const int*)d_in[1];
    const float* enc_W = (const float*)d_in[2];
    const float* enc_b = (const float*)d_in[3];
    const float* W1    = (const float*)d_in[4];
    const float* b1    = (const float*)d_in[5];
    const float* W2    = (const float*)d_in[6];
    const float* b2    = (const float*)d_in[7];
    const float* W3    = (const float*)d_in[8];
    const float* b3    = (const float*)d_in[9];
    const float* decW  = (const float*)d_in[10];
    const float* decb  = (const float*)d_in[11];
    float* out = (float*)d_out;

    const int M = in_sizes[0] / 128;   // 50000
    const int E = in_sizes[1] / 2;     // 800000
    const int* src = ei;
    const int* dst = ei + E;

    float *dinv, *csr_w;
    __half *actA, *actB, *hwh, *WhBase;
    int *deg, *offs, *cur, *bsum, *csr_src;
    cudaGetSymbolAddress((void**)&actA,    g_actA);
    cudaGetSymbolAddress((void**)&actB,    g_actB);
    cudaGetSymbolAddress((void**)&hwh,     g_hwh);
    cudaGetSymbolAddress((void**)&WhBase,  g_Wh);
    cudaGetSymbolAddress((void**)&deg,     g_deg);
    cudaGetSymbolAddress((void**)&dinv,    g_dinv);
    cudaGetSymbolAddress((void**)&offs,    g_offs);
    cudaGetSymbolAddress((void**)&cur,     g_cur);
    cudaGetSymbolAddress((void**)&bsum,    g_bsum);
    cudaGetSymbolAddress((void**)&csr_src, g_csr_src);
    cudaGetSymbolAddress((void**)&csr_w,   g_csr_w);

    __half* Wh[4] = {WhBase, WhBase + 65536, WhBase + 2 * 65536, WhBase + 3 * 65536};

    const int nb = (M + 255) / 256;

    // ---- graph preprocessing ----
    deg_zero_kernel<<<nb, 256>>>(deg, M);
    deg_count_kernel<<<(E + 255) / 256, 256>>>(deg, dst, E);
    dinv_kernel<<<nb, 256>>>(dinv, deg, M);
    scan1_kernel<<<nb, 256>>>(deg, offs, bsum, M);
    scan2_kernel<<<1, 256>>>(bsum, offs, nb, M);
    scan3_kernel<<<nb, 256>>>(offs, cur, bsum, M);
    csr_fill_kernel<<<(E + 255) / 256, 256>>>(cur, csr_src, csr_w, src, dst, dinv, E);

    // ---- weight transpose to fp16 + x convert ----
    wsplit_kernel<<<(256 * 128 + 255) / 256, 256>>>(enc_W, Wh[0], 128);
    wsplit_kernel<<<(256 * 256 + 255) / 256, 256>>>(W1,    Wh[1], 256);
    wsplit_kernel<<<(256 * 256 + 255) / 256, 256>>>(W2,    Wh[2], 256);
    wsplit_kernel<<<(256 * 256 + 255) / 256, 256>>>(W3,    Wh[3], 256);
    x16_kernel<<<(M * 32 + 255) / 256, 256>>>(x, hwh, M * 32);   // 128 fp32 per row = 32 float4s

    const dim3 gg((M + 127) / 128, 2);
    const int gat_blocks = (M + 7) / 8;

    // encoder: actA = x16 @ enc_W + enc_b
    gemm_f16_kernel<128, true, false><<<gg, 256>>>(hwh, Wh[0], enc_b, actA, M);

    // conv1: hwh = actA @ W1 ; actB = gather(hwh) + b1
    gemm_f16_kernel<256, false, false><<<gg, 256>>>(actA, Wh[1], nullptr, hwh, M);
    gather_kernel<<<gat_blocks, 256>>>(actB, hwh, offs, csr_src, csr_w, dinv, b1, M);

    // conv2 (relu on A fragments)
    gemm_f16_kernel<256, false, true><<<gg, 256>>>(actB, Wh[2], nullptr, hwh, M);
    gather_kernel<<<gat_blocks, 256>>>(actA, hwh, offs, csr_src, csr_w, dinv, b2, M);

    // conv3
    gemm_f16_kernel<256, false, true><<<gg, 256>>>(actA, Wh[3], nullptr, hwh, M);
    gather_kernel<<<gat_blocks, 256>>>(actB, hwh, offs, csr_src, csr_w, dinv, b3, M);

    // decoder (relu fused)
    decoder_kernel<<<(M + 7) / 8, 256>>>(actB, decW, decb, out, M);
}

// round 11
// speedup vs baseline: 3.8629x; 1.0214x over previous
#include <cuda_runtime.h>
#include <cuda_fp16.h>
#include <cstdint>

#define NNODES 50000
#define EDGES  800000
#define HDIM   256

// ---------------- scratch (no allocations allowed) ----------------
__device__ __half g_actA[NNODES * HDIM];
__device__ __half g_actB[NNODES * HDIM];
__device__ __half g_hwh[NNODES * HDIM];    // GEMM out for convs; also holds x16 for encoder
__device__ __half g_Wh[4][65536];
__device__ int    g_deg[NNODES];
__device__ float  g_dinv[NNODES];
__device__ int    g_offs[NNODES + 1];
__device__ int    g_cur[NNODES];
__device__ int    g_bsum[256];
__device__ int    g_csr_src[EDGES];
__device__ float  g_csr_w[EDGES];

// ---------------- degree ----------------
__global__ void deg_zero_kernel(int* __restrict__ deg, int n) {
    int i = blockIdx.x * blockDim.x + threadIdx.x;
    if (i < n) deg[i] = 0;
}

__global__ void deg_count_kernel(int* __restrict__ deg, const int* __restrict__ dst, int E) {
    int e = blockIdx.x * blockDim.x + threadIdx.x;
    if (e < E) atomicAdd(&deg[dst[e]], 1);
}

// ---------------- 3-pass scan (multi-block); dinv fused into pass 3 ----------------
__global__ void scan1_kernel(const int* __restrict__ deg, int* __restrict__ offs,
                             int* __restrict__ bsum, int n)
{
    __shared__ int sh[256];
    const int t = threadIdx.x;
    const int i = blockIdx.x * 256 + t;
    int v = (i < n) ? deg[i] : 0;
    sh[t] = v;
    __syncthreads();
#pragma unroll
    for (int off = 1; off < 256; off <<= 1) {
        int x = (t >= off) ? sh[t - off] : 0;
        __syncthreads();
        sh[t] += x;
        __syncthreads();
    }
    if (i < n) offs[i] = sh[t] - v;
    if (t == 255) bsum[blockIdx.x] = sh[255];
}

__global__ void scan2_kernel(int* __restrict__ bsum, int* __restrict__ offs, int nb, int n)
{
    __shared__ int sh[256];
    const int t = threadIdx.x;
    int v = (t < nb) ? bsum[t] : 0;
    sh[t] = v;
    __syncthreads();
#pragma unroll
    for (int off = 1; off < 256; off <<= 1) {
        int x = (t >= off) ? sh[t - off] : 0;
        __syncthreads();
        sh[t] += x;
        __syncthreads();
    }
    if (t < nb) bsum[t] = sh[t] - v;
    if (t == 255) offs[n] = sh[255];
}

__global__ void scan3_kernel(int* __restrict__ offs, int* __restrict__ cur,
                             float* __restrict__ dinv, const int* __restrict__ deg,
                             const int* __restrict__ bsum, int n)
{
    int i = blockIdx.x * blockDim.x + threadIdx.x;
    if (i < n) {
        int o = offs[i] + bsum[i >> 8];
        offs[i] = o;
        cur[i]  = o;
        dinv[i] = rsqrtf((float)(deg[i] + 1));   // +1 self-loop
    }
}

// ---------------- CSR fill (w fused) ----------------
__global__ void csr_fill_kernel(int* __restrict__ cur, int* __restrict__ csr_src,
                                float* __restrict__ csr_w,
                                const int* __restrict__ src, const int* __restrict__ dst,
                                const float* __restrict__ dinv, int E)
{
    int e = blockIdx.x * blockDim.x + threadIdx.x;
    if (e >= E) return;
    int s = src[e];
    int p = atomicAdd(&cur[dst[e]], 1);
    csr_src[p] = s;
    csr_w[p]   = dinv[s];
}

// ---------------- weight transpose to fp16 (once per layer) ----------------
__global__ void wsplit_kernel(const float* __restrict__ W, __half* __restrict__ Wh, int K)
{
    int idx = blockIdx.x * 256 + threadIdx.x;   // idx = n*K + k
    if (idx >= 256 * K) return;
    int n = idx / K, k = idx - n * K;
    Wh[idx] = __float2half_rn(W[k * 256 + n]);
}

// ---------------- x -> fp16 convert ----------------
__global__ void x16_kernel(const float* __restrict__ x, __half* __restrict__ xh, int total4)
{
    int i = blockIdx.x * 256 + threadIdx.x;   // over float4s
    if (i >= total4) return;
    float4 v = *(const float4*)(x + 4 * (size_t)i);
    __half2 a = __floats2half2_rn(v.x, v.y);
    __half2 b = __floats2half2_rn(v.z, v.w);
    *(uint2*)(xh + 4 * (size_t)i) = make_uint2(*(uint32_t*)&a, *(uint32_t*)&b);
}

// ---------------- fp16 tensor-core GEMM: 3-stage cp.async + ldmatrix ----------------
// C[M,256] = A[M,K] @ W[K,256] (+bias), fp32 accumulate, fp16 out.
// Tile 128x128, BK=16, 256 threads = 8 warps (4m x 2n), warp tile 32x64.

__device__ __forceinline__ void mma_f16(float* c, const uint32_t* a, uint32_t b0, uint32_t b1) {
    asm volatile("mma.sync.aligned.m16n8k16.row.col.f32.f16.f16.f32 "
        "{%0,%1,%2,%3}, {%4,%5,%6,%7}, {%8,%9}, {%0,%1,%2,%3};"
        : "+f"(c[0]), "+f"(c[1]), "+f"(c[2]), "+f"(c[3])
        : "r"(a[0]), "r"(a[1]), "r"(a[2]), "r"(a[3]), "r"(b0), "r"(b1));
}

__device__ __forceinline__ void ldm_x4(uint32_t* r, uint32_t saddr) {
    asm volatile("ldmatrix.sync.aligned.m8n8.x4.shared.b16 {%0,%1,%2,%3}, [%4];"
        : "=r"(r[0]), "=r"(r[1]), "=r"(r[2]), "=r"(r[3]) : "r"(saddr));
}

__device__ __forceinline__ void cpa16(uint32_t saddr, const void* gaddr, int szr) {
    asm volatile("cp.async.cg.shared.global [%0], [%1], 16, %2;"
        :: "r"(saddr), "l"(gaddr), "r"(szr));
}

template <int K, bool BIAS, bool RELU_A>
__global__ void __launch_bounds__(256) gemm_f16_kernel(
    const __half* __restrict__ A, const __half* __restrict__ Wh,
    const float* __restrict__ bias, __half* __restrict__ Cout, int M)
{
    // [buf(3)][row-or-n][k(16)+pad(8)]; row stride 48B -> conflict-free ldmatrix
    __shared__ __half sA[3][128][24];
    __shared__ __half sB[3][128][24];

    const int tid  = threadIdx.x;
    const int lane = tid & 31;
    const int wid  = tid >> 5;
    const int wm   = wid >> 1;
    const int wn   = wid & 1;
    const int g    = lane >> 2;
    const int tg   = lane & 3;
    const int row0 = blockIdx.x * 128;
    const int col0 = blockIdx.y * 128;

    // loaders: one 16B cp.async per thread per matrix per stage
    const int ar  = tid >> 1;
    const int ak8 = (tid & 1) * 8;
    const int bn  = tid & 127;
    const int bh8 = (tid >> 7) * 8;

    const int arow = row0 + ar;
    const int asz  = (arow < M) ? 16 : 0;       // zero-fill OOB rows
    const __half* Aptr = A + (size_t)arow * K + ak8;
    const __half* Bph  = Wh + (size_t)(col0 + bn) * K + bh8;

    const uint32_t sA_base = (uint32_t)__cvta_generic_to_shared(&sA[0][0][0]);
    const uint32_t sB_base = (uint32_t)__cvta_generic_to_shared(&sB[0][0][0]);
    const uint32_t bufstride = 128 * 48;
    const uint32_t ast = sA_base + ar * 48 + ak8 * 2;
    const uint32_t bst = sB_base + bn * 48 + bh8 * 2;

    // ldmatrix per-lane offsets
    const int l8 = lane & 7;
    const int a_r = ((lane >> 3) & 1) * 8 + l8;
    const int a_k = (lane >> 4) * 8;
    const int b_n = ((lane >> 4) & 1) * 8 + l8;
    const int b_k = ((lane >> 3) & 1) * 8;
    const uint32_t aoff0 = (uint32_t)((wm * 32 + a_r) * 48 + a_k * 2);
    const uint32_t boff0 = (uint32_t)((wn * 64 + b_n) * 48 + b_k * 2);

    float acc[2][8][4];
#pragma unroll
    for (int mt = 0; mt < 2; mt++)
#pragma unroll
        for (int nt = 0; nt < 8; nt++)
#pragma unroll
            for (int r = 0; r < 4; r++) acc[mt][nt][r] = 0.f;

    const int NT = K / 16;

    // prologue: stages 0 and 1 in flight
#pragma unroll
    for (int s = 0; s < 2; s++) {
        const uint32_t nb = s * bufstride;
        cpa16(ast + nb, Aptr + s * 16, asz);
        cpa16(bst + nb, Bph + s * 16, 16);
        asm volatile("cp.async.commit_group;");
    }

    const __half2 zero2 = __float2half2_rn(0.f);

    for (int it = 0; it < NT; it++) {
        const int buf = it % 3;
        asm volatile("cp.async.wait_group 1;");   // stage `it` ready (<=1 group in flight)
        __syncthreads();                          // also: all warps done with buf (it-1)%3

        // issue stage it+2 into buffer (it+2)%3 == (it-1)%3 (safe per sync above)
        if (it + 2 < NT) {
            const int off = (it + 2) * 16;
            const uint32_t nb = ((it + 2) % 3) * bufstride;
            cpa16(ast + nb, Aptr + off, asz);
            cpa16(bst + nb, Bph + off, 16);
        }
        asm volatile("cp.async.commit_group;");   // commit (possibly empty) to keep count

        // A fragments
        uint32_t Af[2][4];
#pragma unroll
        for (int mt = 0; mt < 2; mt++) {
            ldm_x4(Af[mt], sA_base + buf * bufstride + aoff0 + mt * 16 * 48);
            if (RELU_A) {
#pragma unroll
                for (int j = 0; j < 4; j++) {
                    __half2 h = *(__half2*)&Af[mt][j];
                    h = __hmax2(h, zero2);
                    Af[mt][j] = *(uint32_t*)&h;
                }
            }
        }

        // B fragments
        uint32_t Bf[8][2];
#pragma unroll
        for (int q = 0; q < 4; q++) {
            uint32_t r[4];
            ldm_x4(r, sB_base + buf * bufstride + boff0 + q * 16 * 48);
            Bf[2 * q][0]     = r[0]; Bf[2 * q][1]     = r[1];
            Bf[2 * q + 1][0] = r[2]; Bf[2 * q + 1][1] = r[3];
        }

#pragma unroll
        for (int nt = 0; nt < 8; nt++)
#pragma unroll
            for (int mt = 0; mt < 2; mt++)
                mma_f16(acc[mt][nt], Af[mt], Bf[nt][0], Bf[nt][1]);
    }

    // epilogue (fp16 out)
#pragma unroll
    for (int mt = 0; mt < 2; mt++) {
#pragma unroll
        for (int nt = 0; nt < 8; nt++) {
            int r = row0 + wm * 32 + mt * 16 + g;
            int c = col0 + wn * 64 + nt * 8 + 2 * tg;
            float c0 = acc[mt][nt][0], c1 = acc[mt][nt][1];
            float c2 = acc[mt][nt][2], c3 = acc[mt][nt][3];
            if (BIAS) {
                float b0 = bias[c], b1 = bias[c + 1];
                c0 += b0; c1 += b1; c2 += b0; c3 += b1;
            }
            if (r < M)     *(__half2*)(Cout + (size_t)r * HDIM + c)       = __floats2half2_rn(c0, c1);
            if (r + 8 < M) *(__half2*)(Cout + (size_t)(r + 8) * HDIM + c) = __floats2half2_rn(c2, c3);
        }
    }
}

// ---------------- gather conv (fp16 in/out, ReLU fused at store) ----------------
// out = relu( (Σ hw[s]·w)·dinv[d] + hw[d]·dinv[d]² + bias )
template <bool RELU_OUT>
__global__ void __launch_bounds__(256) gather_kernel(
    __half* __restrict__ out, const __half* __restrict__ hw,
    const int* __restrict__ offs, const int* __restrict__ csr_src,
    const float* __restrict__ csr_w, const float* __restrict__ dinv,
    const float* __restrict__ bias, int M)
{
    const int node = blockIdx.x * 8 + (threadIdx.x >> 5);
    if (node >= M) return;
    const int lane = threadIdx.x & 31;
    const int col  = lane * 8;

    const int beg = offs[node];
    const int end = offs[node + 1];

    float acc[8];
#pragma unroll
    for (int i = 0; i < 8; i++) acc[i] = 0.f;

    auto accum = [&](uint4 u, float w) {
        float2 p0 = __half22float2(*(const __half2*)&u.x);
        float2 p1 = __half22float2(*(const __half2*)&u.y);
        float2 p2 = __half22float2(*(const __half2*)&u.z);
        float2 p3 = __half22float2(*(const __half2*)&u.w);
        acc[0] = fmaf(w, p0.x, acc[0]); acc[1] = fmaf(w, p0.y, acc[1]);
        acc[2] = fmaf(w, p1.x, acc[2]); acc[3] = fmaf(w, p1.y, acc[3]);
        acc[4] = fmaf(w, p2.x, acc[4]); acc[5] = fmaf(w, p2.y, acc[5]);
        acc[6] = fmaf(w, p3.x, acc[6]); acc[7] = fmaf(w, p3.y, acc[7]);
    };

    int j = beg;
    for (; j + 1 < end; j += 2) {
        int s0 = csr_src[j], s1 = csr_src[j + 1];
        float w0 = csr_w[j], w1 = csr_w[j + 1];
        uint4 u0 = *(const uint4*)(hw + (size_t)s0 * HDIM + col);
        uint4 u1 = *(const uint4*)(hw + (size_t)s1 * HDIM + col);
        accum(u0, w0);
        accum(u1, w1);
    }
    if (j < end) {
        uint4 u0 = *(const uint4*)(hw + (size_t)csr_src[j] * HDIM + col);
        accum(u0, csr_w[j]);
    }

    const float dd = dinv[node];
    const float ds = dd * dd;
    uint4 su = *(const uint4*)(hw + (size_t)node * HDIM + col);
    float2 s0 = __half22float2(*(const __half2*)&su.x);
    float2 s1 = __half22float2(*(const __half2*)&su.y);
    float2 s2 = __half22float2(*(const __half2*)&su.z);
    float2 s3 = __half22float2(*(const __half2*)&su.w);
    float sf[8] = {s0.x, s0.y, s1.x, s1.y, s2.x, s2.y, s3.x, s3.y};

    float4 bb0 = *(const float4*)(bias + col);
    float4 bb1 = *(const float4*)(bias + col + 4);
    float bf[8] = {bb0.x, bb0.y, bb0.z, bb0.w, bb1.x, bb1.y, bb1.z, bb1.w};

    __half2 o[4];
#pragma unroll
    for (int i = 0; i < 4; i++) {
        float e0 = fmaf(acc[2*i],   dd, fmaf(sf[2*i],   ds, bf[2*i]));
        float e1 = fmaf(acc[2*i+1], dd, fmaf(sf[2*i+1], ds, bf[2*i+1]));
        if (RELU_OUT) { e0 = fmaxf(e0, 0.f); e1 = fmaxf(e1, 0.f); }
        o[i] = __floats2half2_rn(e0, e1);
    }
    *(uint4*)(out + (size_t)node * HDIM + col) = *(uint4*)o;
}

// ---------------- decoder: out[i] = relu(h[i,:]) . dec_W + dec_b ----------------
__global__ void __launch_bounds__(256) decoder_kernel(
    const __half* __restrict__ h, const float* __restrict__ dw,
    const float* __restrict__ db, float* __restrict__ out, int M)
{
    int row  = blockIdx.x * (blockDim.x >> 5) + (threadIdx.x >> 5);
    int lane = threadIdx.x & 31;
    if (row >= M) return;
    const __half* hr = h + (size_t)row * HDIM;
    float s = 0.f;
#pragma unroll
    for (int i = 0; i < 8; i++) {
        float v = fmaxf(__half2float(hr[lane + i * 32]), 0.f);
        s = fmaf(v, __ldg(&dw[lane + i * 32]), s);
    }
#pragma unroll
    for (int o = 16; o > 0; o >>= 1) s += __shfl_xor_sync(0xffffffffu, s, o);
    if (lane == 0) out[row] = s + db[0];
}

// ---------------- launch ----------------
extern "C" void kernel_launch(void* const* d_in, const int* in_sizes, int n_in,
                              void* d_out, int out_size)
{
    const float* x     = (const float*)d_in[0];
    const int*   ei    = (const int*)d_in[1];
    const float* enc_W = (const float*)d_in[2];
    const float* enc_b = (const float*)d_in[3];
    const float* W1    = (const float*)d_in[4];
    const float* b1    = (const float*)d_in[5];
    const float* W2    = (const float*)d_in[6];
    const float* b2    = (const float*)d_in[7];
    const float* W3    = (const float*)d_in[8];
    const float* b3    = (const float*)d_in[9];
    const float* decW  = (const float*)d_in[10];
    const float* decb  = (const float*)d_in[11];
    float* out = (float*)d_out;

    const int M = in_sizes[0] / 128;   // 50000
    const int E = in_sizes[1] / 2;     // 800000
    const int* src = ei;
    const int* dst = ei + E;

    float *dinv, *csr_w;
    __half *actA, *actB, *hwh, *WhBase;
    int *deg, *offs, *cur, *bsum, *csr_src;
    cudaGetSymbolAddress((void**)&actA,    g_actA);
    cudaGetSymbolAddress((void**)&actB,    g_actB);
    cudaGetSymbolAddress((void**)&hwh,     g_hwh);
    cudaGetSymbolAddress((void**)&WhBase,  g_Wh);
    cudaGetSymbolAddress((void**)&deg,     g_deg);
    cudaGetSymbolAddress((void**)&dinv,    g_dinv);
    cudaGetSymbolAddress((void**)&offs,    g_offs);
    cudaGetSymbolAddress((void**)&cur,     g_cur);
    cudaGetSymbolAddress((void**)&bsum,    g_bsum);
    cudaGetSymbolAddress((void**)&csr_src, g_csr_src);
    cudaGetSymbolAddress((void**)&csr_w,   g_csr_w);

    __half* Wh[4] = {WhBase, WhBase + 65536, WhBase + 2 * 65536, WhBase + 3 * 65536};

    const int nb = (M + 255) / 256;

    // ---- graph preprocessing ----
    deg_zero_kernel<<<nb, 256>>>(deg, M);
    deg_count_kernel<<<(E + 255) / 256, 256>>>(deg, dst, E);
    scan1_kernel<<<nb, 256>>>(deg, offs, bsum, M);
    scan2_kernel<<<1, 256>>>(bsum, offs, nb, M);
    scan3_kernel<<<nb, 256>>>(offs, cur, dinv, deg, bsum, M);
    csr_fill_kernel<<<(E + 255) / 256, 256>>>(cur, csr_src, csr_w, src, dst, dinv, E);

    // ---- weight transpose to fp16 + x convert ----
    wsplit_kernel<<<(256 * 128 + 255) / 256, 256>>>(enc_W, Wh[0], 128);
    wsplit_kernel<<<(256 * 256 + 255) / 256, 256>>>(W1,    Wh[1], 256);
    wsplit_kernel<<<(256 * 256 + 255) / 256, 256>>>(W2,    Wh[2], 256);
    wsplit_kernel<<<(256 * 256 + 255) / 256, 256>>>(W3,    Wh[3], 256);
    x16_kernel<<<(M * 32 + 255) / 256, 256>>>(x, hwh, M * 32);

    const dim3 gg((M + 127) / 128, 2);
    const int gat_blocks = (M + 7) / 8;

    // encoder: actA = x16 @ enc_W + enc_b
    gemm_f16_kernel<128, true, false><<<gg, 256>>>(hwh, Wh[0], enc_b, actA, M);

    // conv1: hwh = actA @ W1 ; actB = relu(gather(hwh) + b1)
    gemm_f16_kernel<256, false, false><<<gg, 256>>>(actA, Wh[1], nullptr, hwh, M);
    gather_kernel<true><<<gat_blocks, 256>>>(actB, hwh, offs, csr_src, csr_w, dinv, b1, M);

    // conv2 (input already relu'd)
    gemm_f16_kernel<256, false, false><<<gg, 256>>>(actB, Wh[2], nullptr, hwh, M);
    gather_kernel<true><<<gat_blocks, 256>>>(actA, hwh, offs, csr_src, csr_w, dinv, b2, M);

    // conv3
    gemm_f16_kernel<256, false, false><<<gg, 256>>>(actA, Wh[3], nullptr, hwh, M);
    gather_kernel<true><<<gat_blocks, 256>>>(actB, hwh, offs, csr_src, csr_w, dinv, b3, M);

    // decoder (relu idempotent on relu'd input)
    decoder_kernel<<<(M + 7) / 8, 256>>>(actB, decW, decb, out, M);
}

// round 12
// speedup vs baseline: 4.0473x; 1.0478x over previous
#include <cuda_runtime.h>
#include <cuda_fp16.h>
#include <cstdint>

#define NNODES 50000
#define EDGES  800000
#define HDIM   256

// ---------------- scratch (no allocations allowed) ----------------
__device__ __half g_actA[NNODES * HDIM];
__device__ __half g_actB[NNODES * HDIM];
__device__ __half g_hwh[NNODES * HDIM];    // GEMM out for convs; also holds x16 for encoder
__device__ __half g_Wh[4][65536];
__device__ int    g_deg[NNODES];
__device__ float  g_dinv[NNODES];
__device__ int    g_offs[NNODES + 1];
__device__ int    g_cur[NNODES];
__device__ int    g_bsum[256];
__device__ int2   g_csr[EDGES];            // .x = src node, .y = dinv[src] bits

// ---------------- fused prep: deg_zero + 4x weight transpose + x->fp16 ----------------
// item layout: [0, 229376) wsplit (enc 32768 + 3x65536) ; [229376, 279376) deg zero ;
//              [279376, 679376) x16 (float4 granules)
__global__ void prep_kernel(const float* __restrict__ enc_W, const float* __restrict__ W1,
                            const float* __restrict__ W2, const float* __restrict__ W3,
                            __half* __restrict__ WhBase,
                            int* __restrict__ deg,
                            const float* __restrict__ x, __half* __restrict__ xh,
                            int M)
{
    int i = blockIdx.x * 256 + threadIdx.x;
    if (i < 229376) {
        // weight transpose to fp16, n-major
        const float* W; __half* Wh; int K; int idx;
        if (i < 32768)       { W = enc_W; Wh = WhBase;              K = 128; idx = i; }
        else if (i < 98304)  { W = W1;    Wh = WhBase + 65536;      K = 256; idx = i - 32768; }
        else if (i < 163840) { W = W2;    Wh = WhBase + 2 * 65536;  K = 256; idx = i - 98304; }
        else                 { W = W3;    Wh = WhBase + 3 * 65536;  K = 256; idx = i - 163840; }
        int n = idx / K, k = idx - n * K;
        Wh[idx] = __float2half_rn(W[k * 256 + n]);
    } else if (i < 279376) {
        int node = i - 229376;
        if (node < M) deg[node] = 0;
    } else {
        int f4 = i - 279376;                  // over float4s of x [M*128 floats]
        if (f4 < M * 32) {
            float4 v = *(const float4*)(x + 4 * (size_t)f4);
            __half2 a = __floats2half2_rn(v.x, v.y);
            __half2 b = __floats2half2_rn(v.z, v.w);
            *(uint2*)(xh + 4 * (size_t)f4) = make_uint2(*(uint32_t*)&a, *(uint32_t*)&b);
        }
    }
}

__global__ void deg_count_kernel(int* __restrict__ deg, const int* __restrict__ dst, int E) {
    int e = blockIdx.x * blockDim.x + threadIdx.x;
    if (e < E) atomicAdd(&deg[dst[e]], 1);
}

// ---------------- 3-pass scan (multi-block); dinv fused into pass 3 ----------------
__global__ void scan1_kernel(const int* __restrict__ deg, int* __restrict__ offs,
                             int* __restrict__ bsum, int n)
{
    __shared__ int sh[256];
    const int t = threadIdx.x;
    const int i = blockIdx.x * 256 + t;
    int v = (i < n) ? deg[i] : 0;
    sh[t] = v;
    __syncthreads();
#pragma unroll
    for (int off = 1; off < 256; off <<= 1) {
        int x = (t >= off) ? sh[t - off] : 0;
        __syncthreads();
        sh[t] += x;
        __syncthreads();
    }
    if (i < n) offs[i] = sh[t] - v;
    if (t == 255) bsum[blockIdx.x] = sh[255];
}

__global__ void scan2_kernel(int* __restrict__ bsum, int* __restrict__ offs, int nb, int n)
{
    __shared__ int sh[256];
    const int t = threadIdx.x;
    int v = (t < nb) ? bsum[t] : 0;
    sh[t] = v;
    __syncthreads();
#pragma unroll
    for (int off = 1; off < 256; off <<= 1) {
        int x = (t >= off) ? sh[t - off] : 0;
        __syncthreads();
        sh[t] += x;
        __syncthreads();
    }
    if (t < nb) bsum[t] = sh[t] - v;
    if (t == 255) offs[n] = sh[255];
}

__global__ void scan3_kernel(int* __restrict__ offs, int* __restrict__ cur,
                             float* __restrict__ dinv, const int* __restrict__ deg,
                             const int* __restrict__ bsum, int n)
{
    int i = blockIdx.x * blockDim.x + threadIdx.x;
    if (i < n) {
        int o = offs[i] + bsum[i >> 8];
        offs[i] = o;
        cur[i]  = o;
        dinv[i] = rsqrtf((float)(deg[i] + 1));   // +1 self-loop
    }
}

// ---------------- CSR fill (packed src+weight, one 8B scattered write) ----------------
__global__ void csr_fill_kernel(int* __restrict__ cur, int2* __restrict__ csr,
                                const int* __restrict__ src, const int* __restrict__ dst,
                                const float* __restrict__ dinv, int E)
{
    int e = blockIdx.x * blockDim.x + threadIdx.x;
    if (e >= E) return;
    int s = src[e];
    int p = atomicAdd(&cur[dst[e]], 1);
    csr[p] = make_int2(s, __float_as_int(dinv[s]));
}

// ---------------- fp16 tensor-core GEMM: 3-stage cp.async + ldmatrix ----------------
// C[M,256] = A[M,K] @ W[K,256] (+bias), fp32 accumulate, fp16 out.
// Tile 128x128, BK=16, 256 threads = 8 warps (4m x 2n), warp tile 32x64.

__device__ __forceinline__ void mma_f16(float* c, const uint32_t* a, uint32_t b0, uint32_t b1) {
    asm volatile("mma.sync.aligned.m16n8k16.row.col.f32.f16.f16.f32 "
        "{%0,%1,%2,%3}, {%4,%5,%6,%7}, {%8,%9}, {%0,%1,%2,%3};"
        : "+f"(c[0]), "+f"(c[1]), "+f"(c[2]), "+f"(c[3])
        : "r"(a[0]), "r"(a[1]), "r"(a[2]), "r"(a[3]), "r"(b0), "r"(b1));
}

__device__ __forceinline__ void ldm_x4(uint32_t* r, uint32_t saddr) {
    asm volatile("ldmatrix.sync.aligned.m8n8.x4.shared.b16 {%0,%1,%2,%3}, [%4];"
        : "=r"(r[0]), "=r"(r[1]), "=r"(r[2]), "=r"(r[3]) : "r"(saddr));
}

__device__ __forceinline__ void cpa16(uint32_t saddr, const void* gaddr, int szr) {
    asm volatile("cp.async.cg.shared.global [%0], [%1], 16, %2;"
        :: "r"(saddr), "l"(gaddr), "r"(szr));
}

template <int K, bool BIAS>
__global__ void __launch_bounds__(256) gemm_f16_kernel(
    const __half* __restrict__ A, const __half* __restrict__ Wh,
    const float* __restrict__ bias, __half* __restrict__ Cout, int M)
{
    // [buf(3)][row-or-n][k(16)+pad(8)]; row stride 48B -> conflict-free ldmatrix
    __shared__ __half sA[3][128][24];
    __shared__ __half sB[3][128][24];

    const int tid  = threadIdx.x;
    const int lane = tid & 31;
    const int wid  = tid >> 5;
    const int wm   = wid >> 1;
    const int wn   = wid & 1;
    const int g    = lane >> 2;
    const int tg   = lane & 3;
    const int row0 = blockIdx.x * 128;
    const int col0 = blockIdx.y * 128;

    // loaders: one 16B cp.async per thread per matrix per stage
    const int ar  = tid >> 1;
    const int ak8 = (tid & 1) * 8;
    const int bn  = tid & 127;
    const int bh8 = (tid >> 7) * 8;

    const int arow = row0 + ar;
    const int asz  = (arow < M) ? 16 : 0;       // zero-fill OOB rows
    const __half* Aptr = A + (size_t)arow * K + ak8;
    const __half* Bph  = Wh + (size_t)(col0 + bn) * K + bh8;

    const uint32_t sA_base = (uint32_t)__cvta_generic_to_shared(&sA[0][0][0]);
    const uint32_t sB_base = (uint32_t)__cvta_generic_to_shared(&sB[0][0][0]);
    const uint32_t bufstride = 128 * 48;
    const uint32_t ast = sA_base + ar * 48 + ak8 * 2;
    const uint32_t bst = sB_base + bn * 48 + bh8 * 2;

    // ldmatrix per-lane offsets
    const int l8 = lane & 7;
    const int a_r = ((lane >> 3) & 1) * 8 + l8;
    const int a_k = (lane >> 4) * 8;
    const int b_n = ((lane >> 4) & 1) * 8 + l8;
    const int b_k = ((lane >> 3) & 1) * 8;
    const uint32_t aoff0 = (uint32_t)((wm * 32 + a_r) * 48 + a_k * 2);
    const uint32_t boff0 = (uint32_t)((wn * 64 + b_n) * 48 + b_k * 2);

    float acc[2][8][4];
#pragma unroll
    for (int mt = 0; mt < 2; mt++)
#pragma unroll
        for (int nt = 0; nt < 8; nt++)
#pragma unroll
            for (int r = 0; r < 4; r++) acc[mt][nt][r] = 0.f;

    const int NT = K / 16;

    // prologue: stages 0 and 1 in flight
#pragma unroll
    for (int s = 0; s < 2; s++) {
        const uint32_t nb = s * bufstride;
        cpa16(ast + nb, Aptr + s * 16, asz);
        cpa16(bst + nb, Bph + s * 16, 16);
        asm volatile("cp.async.commit_group;");
    }

    for (int it = 0; it < NT; it++) {
        const int buf = it % 3;
        asm volatile("cp.async.wait_group 1;");   // stage `it` ready
        __syncthreads();                          // all warps done with buf (it-1)%3

        if (it + 2 < NT) {
            const int off = (it + 2) * 16;
            const uint32_t nb = ((it + 2) % 3) * bufstride;
            cpa16(ast + nb, Aptr + off, asz);
            cpa16(bst + nb, Bph + off, 16);
        }
        asm volatile("cp.async.commit_group;");   // keep group count aligned

        uint32_t Af[2][4];
#pragma unroll
        for (int mt = 0; mt < 2; mt++)
            ldm_x4(Af[mt], sA_base + buf * bufstride + aoff0 + mt * 16 * 48);

        uint32_t Bf[8][2];
#pragma unroll
        for (int q = 0; q < 4; q++) {
            uint32_t r[4];
            ldm_x4(r, sB_base + buf * bufstride + boff0 + q * 16 * 48);
            Bf[2 * q][0]     = r[0]; Bf[2 * q][1]     = r[1];
            Bf[2 * q + 1][0] = r[2]; Bf[2 * q + 1][1] = r[3];
        }

#pragma unroll
        for (int nt = 0; nt < 8; nt++)
#pragma unroll
            for (int mt = 0; mt < 2; mt++)
                mma_f16(acc[mt][nt], Af[mt], Bf[nt][0], Bf[nt][1]);
    }

    // epilogue (fp16 out)
#pragma unroll
    for (int mt = 0; mt < 2; mt++) {
#pragma unroll
        for (int nt = 0; nt < 8; nt++) {
            int r = row0 + wm * 32 + mt * 16 + g;
            int c = col0 + wn * 64 + nt * 8 + 2 * tg;
            float c0 = acc[mt][nt][0], c1 = acc[mt][nt][1];
            float c2 = acc[mt][nt][2], c3 = acc[mt][nt][3];
            if (BIAS) {
                float b0 = bias[c], b1 = bias[c + 1];
                c0 += b0; c1 += b1; c2 += b0; c3 += b1;
            }
            if (r < M)     *(__half2*)(Cout + (size_t)r * HDIM + c)       = __floats2half2_rn(c0, c1);
            if (r + 8 < M) *(__half2*)(Cout + (size_t)(r + 8) * HDIM + c) = __floats2half2_rn(c2, c3);
        }
    }
}

// ---------------- gather conv (fp16 in/out, ReLU fused at store, 4x unroll) ----------------
// out = relu( (Σ hw[s]·w)·dinv[d] + hw[d]·dinv[d]² + bias )
__global__ void __launch_bounds__(256) gather_kernel(
    __half* __restrict__ out, const __half* __restrict__ hw,
    const int* __restrict__ offs, const int2* __restrict__ csr,
    const float* __restrict__ dinv, const float* __restrict__ bias, int M)
{
    const int node = blockIdx.x * 8 + (threadIdx.x >> 5);
    if (node >= M) return;
    const int lane = threadIdx.x & 31;
    const int col  = lane * 8;

    const int beg = offs[node];
    const int end = offs[node + 1];

    float acc[8];
#pragma unroll
    for (int i = 0; i < 8; i++) acc[i] = 0.f;

    auto accum = [&](uint4 u, float w) {
        float2 p0 = __half22float2(*(const __half2*)&u.x);
        float2 p1 = __half22float2(*(const __half2*)&u.y);
        float2 p2 = __half22float2(*(const __half2*)&u.z);
        float2 p3 = __half22float2(*(const __half2*)&u.w);
        acc[0] = fmaf(w, p0.x, acc[0]); acc[1] = fmaf(w, p0.y, acc[1]);
        acc[2] = fmaf(w, p1.x, acc[2]); acc[3] = fmaf(w, p1.y, acc[3]);
        acc[4] = fmaf(w, p2.x, acc[4]); acc[5] = fmaf(w, p2.y, acc[5]);
        acc[6] = fmaf(w, p3.x, acc[6]); acc[7] = fmaf(w, p3.y, acc[7]);
    };

    int j = beg;
    for (; j + 3 < end; j += 4) {
        int2 e0 = csr[j],     e1 = csr[j + 1];
        int2 e2 = csr[j + 2], e3 = csr[j + 3];
        uint4 u0 = *(const uint4*)(hw + (size_t)e0.x * HDIM + col);
        uint4 u1 = *(const uint4*)(hw + (size_t)e1.x * HDIM + col);
        uint4 u2 = *(const uint4*)(hw + (size_t)e2.x * HDIM + col);
        uint4 u3 = *(const uint4*)(hw + (size_t)e3.x * HDIM + col);
        accum(u0, __int_as_float(e0.y));
        accum(u1, __int_as_float(e1.y));
        accum(u2, __int_as_float(e2.y));
        accum(u3, __int_as_float(e3.y));
    }
    for (; j < end; j++) {
        int2 e0 = csr[j];
        uint4 u0 = *(const uint4*)(hw + (size_t)e0.x * HDIM + col);
        accum(u0, __int_as_float(e0.y));
    }

    const float dd = dinv[node];
    const float ds = dd * dd;
    uint4 su = *(const uint4*)(hw + (size_t)node * HDIM + col);
    float2 s0 = __half22float2(*(const __half2*)&su.x);
    float2 s1 = __half22float2(*(const __half2*)&su.y);
    float2 s2 = __half22float2(*(const __half2*)&su.z);
    float2 s3 = __half22float2(*(const __half2*)&su.w);
    float sf[8] = {s0.x, s0.y, s1.x, s1.y, s2.x, s2.y, s3.x, s3.y};

    float4 bb0 = *(const float4*)(bias + col);
    float4 bb1 = *(const float4*)(bias + col + 4);
    float bf[8] = {bb0.x, bb0.y, bb0.z, bb0.w, bb1.x, bb1.y, bb1.z, bb1.w};

    __half2 o[4];
#pragma unroll
    for (int i = 0; i < 4; i++) {
        float e0 = fmaxf(fmaf(acc[2*i],   dd, fmaf(sf[2*i],   ds, bf[2*i])),   0.f);
        float e1 = fmaxf(fmaf(acc[2*i+1], dd, fmaf(sf[2*i+1], ds, bf[2*i+1])), 0.f);
        o[i] = __floats2half2_rn(e0, e1);
    }
    *(uint4*)(out + (size_t)node * HDIM + col) = *(uint4*)o;
}

// ---------------- decoder: out[i] = relu(h[i,:]) . dec_W + dec_b ----------------
__global__ void __launch_bounds__(256) decoder_kernel(
    const __half* __restrict__ h, const float* __restrict__ dw,
    const float* __restrict__ db, float* __restrict__ out, int M)
{
    int row  = blockIdx.x * (blockDim.x >> 5) + (threadIdx.x >> 5);
    int lane = threadIdx.x & 31;
    if (row >= M) return;
    const __half* hr = h + (size_t)row * HDIM;
    float s = 0.f;
#pragma unroll
    for (int i = 0; i < 8; i++) {
        float v = fmaxf(__half2float(hr[lane + i * 32]), 0.f);  // idempotent on relu'd input
        s = fmaf(v, __ldg(&dw[lane + i * 32]), s);
    }
#pragma unroll
    for (int o = 16; o > 0; o >>= 1) s += __shfl_xor_sync(0xffffffffu, s, o);
    if (lane == 0) out[row] = s + db[0];
}

// ---------------- launch ----------------
extern "C" void kernel_launch(void* const* d_in, const int* in_sizes, int n_in,
                              void* d_out, int out_size)
{
    const float* x     = (const float*)d_in[0];
    const int*   ei    = (const int*)d_in[1];
    const float* enc_W = (const float*)d_in[2];
    const float* enc_b = (const float*)d_in[3];
    const float* W1    = (const float*)d_in[4];
    const float* b1    = (const float*)d_in[5];
    const float* W2    = (const float*)d_in[6];
    const float* b2    = (const float*)d_in[7];
    const float* W3    = (const float*)d_in[8];
    const float* b3    = (const float*)d_in[9];
    const float* decW  = (const float*)d_in[10];
    const float* decb  = (const float*)d_in[11];
    float* out = (float*)d_out;

    const int M = in_sizes[0] / 128;   // 50000
    const int E = in_sizes[1] / 2;     // 800000
    const int* src = ei;
    const int* dst = ei + E;

    float *dinv;
    __half *actA, *actB, *hwh, *WhBase;
    int *deg, *offs, *cur, *bsum;
    int2 *csr;
    cudaGetSymbolAddress((void**)&actA,   g_actA);
    cudaGetSymbolAddress((void**)&actB,   g_actB);
    cudaGetSymbolAddress((void**)&hwh,    g_hwh);
    cudaGetSymbolAddress((void**)&WhBase, g_Wh);
    cudaGetSymbolAddress((void**)&deg,    g_deg);
    cudaGetSymbolAddress((void**)&dinv,   g_dinv);
    cudaGetSymbolAddress((void**)&offs,   g_offs);
    cudaGetSymbolAddress((void**)&cur,    g_cur);
    cudaGetSymbolAddress((void**)&bsum,   g_bsum);
    cudaGetSymbolAddress((void**)&csr,    g_csr);

    const int nb = (M + 255) / 256;

    // ---- fused prep (deg zero + 4x wsplit + x16) ----
    const int prep_items = 229376 + 50000 + M * 32;
    prep_kernel<<<(prep_items + 255) / 256, 256>>>(enc_W, W1, W2, W3, WhBase, deg, x, hwh, M);

    // ---- graph preprocessing ----
    deg_count_kernel<<<(E + 255) / 256, 256>>>(deg, dst, E);
    scan1_kernel<<<nb, 256>>>(deg, offs, bsum, M);
    scan2_kernel<<<1, 256>>>(bsum, offs, nb, M);
    scan3_kernel<<<nb, 256>>>(offs, cur, dinv, deg, bsum, M);
    csr_fill_kernel<<<(E + 255) / 256, 256>>>(cur, csr, src, dst, dinv, E);

    const dim3 gg((M + 127) / 128, 2);
    const int gat_blocks = (M + 7) / 8;

    // encoder: actA = x16 @ enc_W + enc_b
    gemm_f16_kernel<128, true><<<gg, 256>>>(hwh, WhBase, enc_b, actA, M);

    // conv1: hwh = actA @ W1 ; actB = relu(gather(hwh) + b1)
    gemm_f16_kernel<256, false><<<gg, 256>>>(actA, WhBase + 65536, nullptr, hwh, M);
    gather_kernel<<<gat_blocks, 256>>>(actB, hwh, offs, csr, dinv, b1, M);

    // conv2
    gemm_f16_kernel<256, false><<<gg, 256>>>(actB, WhBase + 2 * 65536, nullptr, hwh, M);
    gather_kernel<<<gat_blocks, 256>>>(actA, hwh, offs, csr, dinv, b2, M);

    // conv3
    gemm_f16_kernel<256, false><<<gg, 256>>>(actA, WhBase + 3 * 65536, nullptr, hwh, M);
    gather_kernel<<<gat_blocks, 256>>>(actB, hwh, offs, csr, dinv, b3, M);

    // decoder
    decoder_kernel<<<(M + 7) / 8, 256>>>(actB, decW, decb, out, M);
}

// round 13
// speedup vs baseline: 4.3530x; 1.0755x over previous
#include <cuda_runtime.h>
#include <cuda_fp16.h>
#include <cstdint>

#define NNODES 50000
#define EDGES  800000
#define HDIM   256

// ---------------- scratch (no allocations allowed) ----------------
__device__ __half g_actA[NNODES * HDIM];
__device__ __half g_actB[NNODES * HDIM];
__device__ __half g_hwh[NNODES * HDIM];    // GEMM out for convs; also holds x16 for encoder
__device__ __half g_Wh[4][65536];
__device__ int    g_deg[NNODES];
__device__ float  g_dinv[NNODES];
__device__ int    g_offs[NNODES + 1];
__device__ int    g_cur[NNODES];
__device__ int    g_bsum[256];
__device__ int2   g_csr[EDGES];            // .x = src node, .y = dinv[src] bits

// ---------------- fused prep: deg_zero + 4x weight transpose + x->fp16 ----------------
__global__ void prep_kernel(const float* __restrict__ enc_W, const float* __restrict__ W1,
                            const float* __restrict__ W2, const float* __restrict__ W3,
                            __half* __restrict__ WhBase,
                            int* __restrict__ deg,
                            const float* __restrict__ x, __half* __restrict__ xh,
                            int M)
{
    int i = blockIdx.x * 256 + threadIdx.x;
    if (i < 229376) {
        const float* W; __half* Wh; int K; int idx;
        if (i < 32768)       { W = enc_W; Wh = WhBase;              K = 128; idx = i; }
        else if (i < 98304)  { W = W1;    Wh = WhBase + 65536;      K = 256; idx = i - 32768; }
        else if (i < 163840) { W = W2;    Wh = WhBase + 2 * 65536;  K = 256; idx = i - 98304; }
        else                 { W = W3;    Wh = WhBase + 3 * 65536;  K = 256; idx = i - 163840; }
        int n = idx / K, k = idx - n * K;
        Wh[idx] = __float2half_rn(W[k * 256 + n]);
    } else if (i < 279376) {
        int node = i - 229376;
        if (node < M) deg[node] = 0;
    } else {
        int f4 = i - 279376;
        if (f4 < M * 32) {
            float4 v = *(const float4*)(x + 4 * (size_t)f4);
            __half2 a = __floats2half2_rn(v.x, v.y);
            __half2 b = __floats2half2_rn(v.z, v.w);
            *(uint2*)(xh + 4 * (size_t)f4) = make_uint2(*(uint32_t*)&a, *(uint32_t*)&b);
        }
    }
}

__global__ void deg_count_kernel(int* __restrict__ deg, const int* __restrict__ dst, int E) {
    int e = blockIdx.x * blockDim.x + threadIdx.x;
    if (e < E) atomicAdd(&deg[dst[e]], 1);
}

// ---------------- 3-pass scan (multi-block); dinv fused into pass 3 ----------------
__global__ void scan1_kernel(const int* __restrict__ deg, int* __restrict__ offs,
                             int* __restrict__ bsum, int n)
{
    __shared__ int sh[256];
    const int t = threadIdx.x;
    const int i = blockIdx.x * 256 + t;
    int v = (i < n) ? deg[i] : 0;
    sh[t] = v;
    __syncthreads();
#pragma unroll
    for (int off = 1; off < 256; off <<= 1) {
        int x = (t >= off) ? sh[t - off] : 0;
        __syncthreads();
        sh[t] += x;
        __syncthreads();
    }
    if (i < n) offs[i] = sh[t] - v;
    if (t == 255) bsum[blockIdx.x] = sh[255];
}

__global__ void scan2_kernel(int* __restrict__ bsum, int* __restrict__ offs, int nb, int n)
{
    __shared__ int sh[256];
    const int t = threadIdx.x;
    int v = (t < nb) ? bsum[t] : 0;
    sh[t] = v;
    __syncthreads();
#pragma unroll
    for (int off = 1; off < 256; off <<= 1) {
        int x = (t >= off) ? sh[t - off] : 0;
        __syncthreads();
        sh[t] += x;
        __syncthreads();
    }
    if (t < nb) bsum[t] = sh[t] - v;
    if (t == 255) offs[n] = sh[255];
}

__global__ void scan3_kernel(int* __restrict__ offs, int* __restrict__ cur,
                             float* __restrict__ dinv, const int* __restrict__ deg,
                             const int* __restrict__ bsum, int n)
{
    int i = blockIdx.x * blockDim.x + threadIdx.x;
    if (i < n) {
        int o = offs[i] + bsum[i >> 8];
        offs[i] = o;
        cur[i]  = o;
        dinv[i] = rsqrtf((float)(deg[i] + 1));   // +1 self-loop
    }
}

// ---------------- CSR fill (packed src+weight) ----------------
__global__ void csr_fill_kernel(int* __restrict__ cur, int2* __restrict__ csr,
                                const int* __restrict__ src, const int* __restrict__ dst,
                                const float* __restrict__ dinv, int E)
{
    int e = blockIdx.x * blockDim.x + threadIdx.x;
    if (e >= E) return;
    int s = src[e];
    int p = atomicAdd(&cur[dst[e]], 1);
    csr[p] = make_int2(s, __float_as_int(dinv[s]));
}

// ---------------- fp16 tensor-core GEMM: 3-stage cp.async + ldmatrix ----------------
__device__ __forceinline__ void mma_f16(float* c, const uint32_t* a, uint32_t b0, uint32_t b1) {
    asm volatile("mma.sync.aligned.m16n8k16.row.col.f32.f16.f16.f32 "
        "{%0,%1,%2,%3}, {%4,%5,%6,%7}, {%8,%9}, {%0,%1,%2,%3};"
        : "+f"(c[0]), "+f"(c[1]), "+f"(c[2]), "+f"(c[3])
        : "r"(a[0]), "r"(a[1]), "r"(a[2]), "r"(a[3]), "r"(b0), "r"(b1));
}

__device__ __forceinline__ void ldm_x4(uint32_t* r, uint32_t saddr) {
    asm volatile("ldmatrix.sync.aligned.m8n8.x4.shared.b16 {%0,%1,%2,%3}, [%4];"
        : "=r"(r[0]), "=r"(r[1]), "=r"(r[2]), "=r"(r[3]) : "r"(saddr));
}

__device__ __forceinline__ void cpa16(uint32_t saddr, const void* gaddr, int szr) {
    asm volatile("cp.async.cg.shared.global [%0], [%1], 16, %2;"
        :: "r"(saddr), "l"(gaddr), "r"(szr));
}

template <int K, bool BIAS>
__global__ void __launch_bounds__(256) gemm_f16_kernel(
    const __half* __restrict__ A, const __half* __restrict__ Wh,
    const float* __restrict__ bias, __half* __restrict__ Cout, int M)
{
    __shared__ __half sA[3][128][24];
    __shared__ __half sB[3][128][24];

    const int tid  = threadIdx.x;
    const int lane = tid & 31;
    const int wid  = tid >> 5;
    const int wm   = wid >> 1;
    const int wn   = wid & 1;
    const int g    = lane >> 2;
    const int tg   = lane & 3;
    const int row0 = blockIdx.x * 128;
    const int col0 = blockIdx.y * 128;

    const int ar  = tid >> 1;
    const int ak8 = (tid & 1) * 8;
    const int bn  = tid & 127;
    const int bh8 = (tid >> 7) * 8;

    const int arow = row0 + ar;
    const int asz  = (arow < M) ? 16 : 0;
    const __half* Aptr = A + (size_t)arow * K + ak8;
    const __half* Bph  = Wh + (size_t)(col0 + bn) * K + bh8;

    const uint32_t sA_base = (uint32_t)__cvta_generic_to_shared(&sA[0][0][0]);
    const uint32_t sB_base = (uint32_t)__cvta_generic_to_shared(&sB[0][0][0]);
    const uint32_t bufstride = 128 * 48;
    const uint32_t ast = sA_base + ar * 48 + ak8 * 2;
    const uint32_t bst = sB_base + bn * 48 + bh8 * 2;

    const int l8 = lane & 7;
    const int a_r = ((lane >> 3) & 1) * 8 + l8;
    const int a_k = (lane >> 4) * 8;
    const int b_n = ((lane >> 4) & 1) * 8 + l8;
    const int b_k = ((lane >> 3) & 1) * 8;
    const uint32_t aoff0 = (uint32_t)((wm * 32 + a_r) * 48 + a_k * 2);
    const uint32_t boff0 = (uint32_t)((wn * 64 + b_n) * 48 + b_k * 2);

    float acc[2][8][4];
#pragma unroll
    for (int mt = 0; mt < 2; mt++)
#pragma unroll
        for (int nt = 0; nt < 8; nt++)
#pragma unroll
            for (int r = 0; r < 4; r++) acc[mt][nt][r] = 0.f;

    const int NT = K / 16;

#pragma unroll
    for (int s = 0; s < 2; s++) {
        const uint32_t nb = s * bufstride;
        cpa16(ast + nb, Aptr + s * 16, asz);
        cpa16(bst + nb, Bph + s * 16, 16);
        asm volatile("cp.async.commit_group;");
    }

    for (int it = 0; it < NT; it++) {
        const int buf = it % 3;
        asm volatile("cp.async.wait_group 1;");
        __syncthreads();

        if (it + 2 < NT) {
            const int off = (it + 2) * 16;
            const uint32_t nb = ((it + 2) % 3) * bufstride;
            cpa16(ast + nb, Aptr + off, asz);
            cpa16(bst + nb, Bph + off, 16);
        }
        asm volatile("cp.async.commit_group;");

        uint32_t Af[2][4];
#pragma unroll
        for (int mt = 0; mt < 2; mt++)
            ldm_x4(Af[mt], sA_base + buf * bufstride + aoff0 + mt * 16 * 48);

        uint32_t Bf[8][2];
#pragma unroll
        for (int q = 0; q < 4; q++) {
            uint32_t r[4];
            ldm_x4(r, sB_base + buf * bufstride + boff0 + q * 16 * 48);
            Bf[2 * q][0]     = r[0]; Bf[2 * q][1]     = r[1];
            Bf[2 * q + 1][0] = r[2]; Bf[2 * q + 1][1] = r[3];
        }

#pragma unroll
        for (int nt = 0; nt < 8; nt++)
#pragma unroll
            for (int mt = 0; mt < 2; mt++)
                mma_f16(acc[mt][nt], Af[mt], Bf[nt][0], Bf[nt][1]);
    }

#pragma unroll
    for (int mt = 0; mt < 2; mt++) {
#pragma unroll
        for (int nt = 0; nt < 8; nt++) {
            int r = row0 + wm * 32 + mt * 16 + g;
            int c = col0 + wn * 64 + nt * 8 + 2 * tg;
            float c0 = acc[mt][nt][0], c1 = acc[mt][nt][1];
            float c2 = acc[mt][nt][2], c3 = acc[mt][nt][3];
            if (BIAS) {
                float b0 = bias[c], b1 = bias[c + 1];
                c0 += b0; c1 += b1; c2 += b0; c3 += b1;
            }
            if (r < M)     *(__half2*)(Cout + (size_t)r * HDIM + c)       = __floats2half2_rn(c0, c1);
            if (r + 8 < M) *(__half2*)(Cout + (size_t)(r + 8) * HDIM + c) = __floats2half2_rn(c2, c3);
        }
    }
}

// ---------------- gather core (shared by both variants) ----------------
__device__ __forceinline__ void gather_core(
    float* acc, const __half* __restrict__ hw, const int* __restrict__ offs,
    const int2* __restrict__ csr, int node, int col)
{
    const int beg = offs[node];
    const int end = offs[node + 1];

    auto accum = [&](uint4 u, float w) {
        float2 p0 = __half22float2(*(const __half2*)&u.x);
        float2 p1 = __half22float2(*(const __half2*)&u.y);
        float2 p2 = __half22float2(*(const __half2*)&u.z);
        float2 p3 = __half22float2(*(const __half2*)&u.w);
        acc[0] = fmaf(w, p0.x, acc[0]); acc[1] = fmaf(w, p0.y, acc[1]);
        acc[2] = fmaf(w, p1.x, acc[2]); acc[3] = fmaf(w, p1.y, acc[3]);
        acc[4] = fmaf(w, p2.x, acc[4]); acc[5] = fmaf(w, p2.y, acc[5]);
        acc[6] = fmaf(w, p3.x, acc[6]); acc[7] = fmaf(w, p3.y, acc[7]);
    };

    int j = beg;
    for (; j + 3 < end; j += 4) {
        int2 e0 = csr[j],     e1 = csr[j + 1];
        int2 e2 = csr[j + 2], e3 = csr[j + 3];
        uint4 u0 = *(const uint4*)(hw + (size_t)e0.x * HDIM + col);
        uint4 u1 = *(const uint4*)(hw + (size_t)e1.x * HDIM + col);
        uint4 u2 = *(const uint4*)(hw + (size_t)e2.x * HDIM + col);
        uint4 u3 = *(const uint4*)(hw + (size_t)e3.x * HDIM + col);
        accum(u0, __int_as_float(e0.y));
        accum(u1, __int_as_float(e1.y));
        accum(u2, __int_as_float(e2.y));
        accum(u3, __int_as_float(e3.y));
    }
    for (; j < end; j++) {
        int2 e0 = csr[j];
        uint4 u0 = *(const uint4*)(hw + (size_t)e0.x * HDIM + col);
        accum(u0, __int_as_float(e0.y));
    }
}

__device__ __forceinline__ void gather_final(
    float* o, const float* acc, const __half* __restrict__ hw,
    const float* __restrict__ bias, const float* __restrict__ dinv, int node, int col)
{
    const float dd = dinv[node];
    const float ds = dd * dd;
    uint4 su = *(const uint4*)(hw + (size_t)node * HDIM + col);
    float2 s0 = __half22float2(*(const __half2*)&su.x);
    float2 s1 = __half22float2(*(const __half2*)&su.y);
    float2 s2 = __half22float2(*(const __half2*)&su.z);
    float2 s3 = __half22float2(*(const __half2*)&su.w);
    float sf[8] = {s0.x, s0.y, s1.x, s1.y, s2.x, s2.y, s3.x, s3.y};

    float4 bb0 = *(const float4*)(bias + col);
    float4 bb1 = *(const float4*)(bias + col + 4);
    float bf[8] = {bb0.x, bb0.y, bb0.z, bb0.w, bb1.x, bb1.y, bb1.z, bb1.w};

#pragma unroll
    for (int i = 0; i < 8; i++)
        o[i] = fmaxf(fmaf(acc[i], dd, fmaf(sf[i], ds, bf[i])), 0.f);   // ReLU fused
}

// conv gather: fp16 store
__global__ void __launch_bounds__(256) gather_kernel(
    __half* __restrict__ out, const __half* __restrict__ hw,
    const int* __restrict__ offs, const int2* __restrict__ csr,
    const float* __restrict__ dinv, const float* __restrict__ bias, int M)
{
    const int node = blockIdx.x * 8 + (threadIdx.x >> 5);
    if (node >= M) return;
    const int lane = threadIdx.x & 31;
    const int col  = lane * 8;

    float acc[8];
#pragma unroll
    for (int i = 0; i < 8; i++) acc[i] = 0.f;
    gather_core(acc, hw, offs, csr, node, col);

    float o[8];
    gather_final(o, acc, hw, bias, dinv, node, col);

    __half2 h2[4];
#pragma unroll
    for (int i = 0; i < 4; i++) h2[i] = __floats2half2_rn(o[2*i], o[2*i+1]);
    *(uint4*)(out + (size_t)node * HDIM + col) = *(uint4*)h2;
}

// final gather + decoder fused: out[node] = relu(gather).decW + decb
__global__ void __launch_bounds__(256) gather_dec_kernel(
    float* __restrict__ out, const __half* __restrict__ hw,
    const int* __restrict__ offs, const int2* __restrict__ csr,
    const float* __restrict__ dinv, const float* __restrict__ bias,
    const float* __restrict__ dw, const float* __restrict__ db, int M)
{
    const int node = blockIdx.x * 8 + (threadIdx.x >> 5);
    if (node >= M) return;
    const int lane = threadIdx.x & 31;
    const int col  = lane * 8;

    float acc[8];
#pragma unroll
    for (int i = 0; i < 8; i++) acc[i] = 0.f;
    gather_core(acc, hw, offs, csr, node, col);

    float o[8];
    gather_final(o, acc, hw, bias, dinv, node, col);

    float4 w0 = *(const float4*)(dw + col);
    float4 w1 = *(const float4*)(dw + col + 4);
    float s = o[0]*w0.x + o[1]*w0.y + o[2]*w0.z + o[3]*w0.w
            + o[4]*w1.x + o[5]*w1.y + o[6]*w1.z + o[7]*w1.w;
#pragma unroll
    for (int off = 16; off > 0; off >>= 1) s += __shfl_xor_sync(0xffffffffu, s, off);
    if (lane == 0) out[node] = s + db[0];
}

// ---------------- launch ----------------
extern "C" void kernel_launch(void* const* d_in, const int* in_sizes, int n_in,
                              void* d_out, int out_size)
{
    const float* x     = (const float*)d_in[0];
    const int*   ei    = (const int*)d_in[1];
    const float* enc_W = (const float*)d_in[2];
    const float* enc_b = (const float*)d_in[3];
    const float* W1    = (const float*)d_in[4];
    const float* b1    = (const float*)d_in[5];
    const float* W2    = (const float*)d_in[6];
    const float* b2    = (const float*)d_in[7];
    const float* W3    = (const float*)d_in[8];
    const float* b3    = (const float*)d_in[9];
    const float* decW  = (const float*)d_in[10];
    const float* decb  = (const float*)d_in[11];
    float* out = (float*)d_out;

    const int M = in_sizes[0] / 128;   // 50000
    const int E = in_sizes[1] / 2;     // 800000
    const int* src = ei;
    const int* dst = ei + E;

    float *dinv;
    __half *actA, *actB, *hwh, *WhBase;
    int *deg, *offs, *cur, *bsum;
    int2 *csr;
    cudaGetSymbolAddress((void**)&actA,   g_actA);
    cudaGetSymbolAddress((void**)&actB,   g_actB);
    cudaGetSymbolAddress((void**)&hwh,    g_hwh);
    cudaGetSymbolAddress((void**)&WhBase, g_Wh);
    cudaGetSymbolAddress((void**)&deg,    g_deg);
    cudaGetSymbolAddress((void**)&dinv,   g_dinv);
    cudaGetSymbolAddress((void**)&offs,   g_offs);
    cudaGetSymbolAddress((void**)&cur,    g_cur);
    cudaGetSymbolAddress((void**)&bsum,   g_bsum);
    cudaGetSymbolAddress((void**)&csr,    g_csr);

    // lazily created on the FIRST (uncaptured correctness) call; reused in capture
    static cudaStream_t s2 = nullptr;
    static cudaEvent_t evA = nullptr, evB = nullptr;
    if (!s2) {
        cudaStreamCreateWithFlags(&s2, cudaStreamNonBlocking);
        cudaEventCreateWithFlags(&evA, cudaEventDisableTiming);
        cudaEventCreateWithFlags(&evB, cudaEventDisableTiming);
    }

    const int nb = (M + 255) / 256;

    // ---- fused prep (deg zero + wsplit + x16) on main stream ----
    const int prep_items = 229376 + 50000 + M * 32;
    prep_kernel<<<(prep_items + 255) / 256, 256>>>(enc_W, W1, W2, W3, WhBase, deg, x, hwh, M);
    cudaEventRecord(evA, 0);

    // ---- CSR chain on side stream (only gather1 depends on it) ----
    cudaStreamWaitEvent(s2, evA, 0);
    deg_count_kernel<<<(E + 255) / 256, 256, 0, s2>>>(deg, dst, E);
    scan1_kernel<<<nb, 256, 0, s2>>>(deg, offs, bsum, M);
    scan2_kernel<<<1, 256, 0, s2>>>(bsum, offs, nb, M);
    scan3_kernel<<<nb, 256, 0, s2>>>(offs, cur, dinv, deg, bsum, M);
    csr_fill_kernel<<<(E + 255) / 256, 256, 0, s2>>>(cur, csr, src, dst, dinv, E);
    cudaEventRecord(evB, s2);

    const dim3 gg((M + 127) / 128, 2);
    const int gat_blocks = (M + 7) / 8;

    // ---- main stream: encoder + conv1 GEMM overlap the CSR chain ----
    gemm_f16_kernel<128, true><<<gg, 256>>>(hwh, WhBase, enc_b, actA, M);
    gemm_f16_kernel<256, false><<<gg, 256>>>(actA, WhBase + 65536, nullptr, hwh, M);

    // join: gather1 needs CSR
    cudaStreamWaitEvent(0, evB, 0);
    gather_kernel<<<gat_blocks, 256>>>(actB, hwh, offs, csr, dinv, b1, M);

    // conv2
    gemm_f16_kernel<256, false><<<gg, 256>>>(actB, WhBase + 2 * 65536, nullptr, hwh, M);
    gather_kernel<<<gat_blocks, 256>>>(actA, hwh, offs, csr, dinv, b2, M);

    // conv3 + fused gather/decoder
    gemm_f16_kernel<256, false><<<gg, 256>>>(actA, WhBase + 3 * 65536, nullptr, hwh, M);
    gather_dec_kernel<<<gat_blocks, 256>>>(out, hwh, offs, csr, dinv, b3, decW, decb, M);
}